// round 8
// baseline (speedup 1.0000x reference)
#include <cuda_runtime.h>
#include <cuda_bf16.h>
#include <math.h>
#include <stdint.h>

// Problem constants
#define BB    4
#define LL    2048
#define DD    2048
#define NHH   16
#define DHH   128
#define DHRR  64
#define DCC   1024
#define MTOK  (BB*LL)          // 8192
#define BHT   (BB*NHH)         // 64
#define CCW   2176             // ckv(1024) | cq(1024) | kr(64) | pad(64)

typedef __nv_bfloat16 bf16;

// ---------------- device scratch (static, no allocation) ----------------
__device__ float g_qcqr [MTOK*3072];        // qc | qr   (cols 0-2047 | 2048-3071)
__device__ float g_krn  [MTOK];             // ||k_rope||^2 per token
__device__ float g_cos  [LL*32];
__device__ float g_sin  [LL*32];

// packed q/k (bh, l, 192) hi/lo bf16; V^T (bh, dh128, l) hi/lo bf16
__device__ bf16 g_qh [BHT*LL*192];
__device__ bf16 g_ql [BHT*LL*192];
__device__ bf16 g_kh [BHT*LL*192];
__device__ bf16 g_kl [BHT*LL*192];
__device__ bf16 g_vth[BHT*DHH*LL];
__device__ bf16 g_vtl[BHT*DHH*LL];

// A-side activations, hi/lo bf16
__device__ bf16 g_x_hi   [MTOK*DD];
__device__ bf16 g_x_lo   [MTOK*DD];
__device__ bf16 g_cc_hi  [MTOK*CCW];        // ckv | cq | kr | pad
__device__ bf16 g_cc_lo  [MTOK*CCW];
__device__ bf16 g_attn_hi[MTOK*DD];
__device__ bf16 g_attn_lo[MTOK*DD];

// B-side weights, transposed to K-major [N,K], hi/lo bf16, N-concatenated
__device__ bf16 g_wdkdq_hi[CCW*2048],  g_wdkdq_lo[CCW*2048];   // DKV^T | DQ^T | KR^T | pad
__device__ bf16 g_wukv_hi [4096*1024], g_wukv_lo [4096*1024];  // UK^T | UV^T
__device__ bf16 g_wuqqr_hi[3072*1024], g_wuqqr_lo[3072*1024];  // UQ^T | QR^T
__device__ bf16 g_wo_hi   [DD*DD],     g_wo_lo   [DD*DD];

// ---------------- helpers ----------------
__device__ __forceinline__ uint32_t smem_u32(const void* p) {
    uint32_t a;
    asm("{ .reg .u64 t; cvta.to.shared.u64 t, %1; cvt.u32.u64 %0, t; }" : "=r"(a) : "l"(p));
    return a;
}

#define CP_ASYNC16(dst, src) \
    asm volatile("cp.async.cg.shared.global [%0], [%1], 16;" :: "r"(dst), "l"(src))
#define CP_COMMIT() asm volatile("cp.async.commit_group;" ::: "memory")
#define CP_WAIT(n)  asm volatile("cp.async.wait_group %0;" :: "n"(n) : "memory")

#define LDSM4(r0, r1, r2, r3, addr) \
    asm volatile("ldmatrix.sync.aligned.m8n8.x4.shared.b16 {%0,%1,%2,%3}, [%4];" \
                 : "=r"(r0), "=r"(r1), "=r"(r2), "=r"(r3) : "r"(addr))

#define MMA_BF16(c, a, b) \
    asm volatile("mma.sync.aligned.m16n8k16.row.col.f32.bf16.bf16.f32 " \
                 "{%0,%1,%2,%3}, {%4,%5,%6,%7}, {%8,%9}, {%0,%1,%2,%3};" \
                 : "+f"((c)[0]), "+f"((c)[1]), "+f"((c)[2]), "+f"((c)[3]) \
                 : "r"((a)[0]), "r"((a)[1]), "r"((a)[2]), "r"((a)[3]), \
                   "r"((b)[0]), "r"((b)[1]))

__device__ __forceinline__ void split_bf16(float x, bf16& hi, bf16& lo) {
    hi = __float2bfloat16_rn(x);
    lo = __float2bfloat16_rn(x - __bfloat162float(hi));
}
__device__ __forceinline__ uint16_t bfb(bf16 v) { return *(uint16_t*)&v; }

__device__ __forceinline__ void split_pack2(float x, float y, uint32_t& hi, uint32_t& lo) {
    bf16 hx, lx, hy, ly;
    split_bf16(x, hx, lx);
    split_bf16(y, hy, ly);
    hi = ((uint32_t)bfb(hy) << 16) | bfb(hx);
    lo = ((uint32_t)bfb(ly) << 16) | bfb(lx);
}

__device__ __forceinline__ uint32_t swz(int row, int c, int rowbytes) {
    int c2 = (c & ~7) | ((c ^ row) & 7);
    return (uint32_t)(row * rowbytes + c2 * 16);
}

// ---------------- rope tables ----------------
__global__ void rope_table_kernel() {
    int i = blockIdx.x * blockDim.x + threadIdx.x;
    if (i >= LL*32) return;
    int l = i >> 5;
    int j = i & 31;
    double invf = pow(10000.0, -(double)j / 32.0);
    double ang  = (double)l * invf;
    g_cos[i] = (float)cos(ang);
    g_sin[i] = (float)sin(ang);
}

// ---------------- convert fp32 -> hi/lo bf16 ----------------
__global__ void __launch_bounds__(256) conv_hilo(const float* __restrict__ in,
                                                 bf16* __restrict__ hi,
                                                 bf16* __restrict__ lo, int n4) {
    int i = blockIdx.x * blockDim.x + threadIdx.x;
    if (i >= n4) return;
    float4 v = *(const float4*)&in[(size_t)i * 4];
    bf16 h[4], l[4];
    split_bf16(v.x, h[0], l[0]);
    split_bf16(v.y, h[1], l[1]);
    split_bf16(v.z, h[2], l[2]);
    split_bf16(v.w, h[3], l[3]);
    *(uint64_t*)&hi[(size_t)i * 4] = *(uint64_t*)h;
    *(uint64_t*)&lo[(size_t)i * 4] = *(uint64_t*)l;
}

// ---------------- transpose + convert: out[C][R] (hi/lo bf16) = in[R][C] ----------------
__global__ void __launch_bounds__(256) transpose_conv(const float* __restrict__ in,
                                                      bf16* __restrict__ out_hi,
                                                      bf16* __restrict__ out_lo,
                                                      int R, int C) {
    __shared__ float t[32][33];
    int bx = blockIdx.x * 32, by = blockIdx.y * 32;
    int tx = threadIdx.x, ty = threadIdx.y;     // (32, 8)
    int x = bx + tx;
#pragma unroll
    for (int j = 0; j < 32; j += 8)
        t[ty + j][tx] = in[(size_t)(by + ty + j) * C + x];
    __syncthreads();
    int xo = by + tx;
#pragma unroll
    for (int j = 0; j < 32; j += 8) {
        float v = t[tx][ty + j];
        bf16 h, l;
        split_bf16(v, h, l);
        size_t o = (size_t)(bx + ty + j) * R + xo;
        out_hi[o] = h;
        out_lo[o] = l;
    }
}

// ---------------- bf16x3 mma.sync GEMM: generic ----------------
// KRN: blockIdx.x==16 (the kr tile of the down projection) also reduces
// per-token ||k_rope||^2 into g_krn.
template<int BN, bool HILO, bool KRN>
__global__ void __launch_bounds__(256) gemm_bf16x3(const bf16* __restrict__ Ahi,
                                                   const bf16* __restrict__ Alo,
                                                   int lda,
                                                   const bf16* __restrict__ Bhi,
                                                   const bf16* __restrict__ Blo,
                                                   float* __restrict__ C,
                                                   bf16* __restrict__ Chi,
                                                   bf16* __restrict__ Clo,
                                                   int N, int K) {
    constexpr int ABYTES = 128 * 128;
    constexpr int BBYTES = BN * 128;
    constexpr int STAGE  = 2 * ABYTES + 2 * BBYTES;
    constexpr int WN = BN / 4;
    constexpr int NT = WN / 8;

    extern __shared__ __align__(128) char sm[];
    const uint32_t sbase = smem_u32(sm);

    const int tid  = threadIdx.x;
    const int lane = tid & 31;
    const int warp = tid >> 5;
    const int wm   = (warp >> 2) * 64;
    const int wn   = (warp & 3) * WN;
    const int m0   = blockIdx.y * 128;
    const int n0   = blockIdx.x * BN;
    const int NC   = K >> 6;

    auto load_stage = [&](int chunk, int s) {
        uint32_t sa = sbase + s * STAGE;
        const size_t koff = (size_t)chunk * 64;
#pragma unroll
        for (int it = 0; it < 4; it++) {
            int idx = it * 256 + tid;
            int row = idx >> 3, cw = idx & 7;
            uint32_t off = (uint32_t)(row * 128 + cw * 16);
            off ^= (off >> 3) & 0x70;
            const size_t gofs = (size_t)(m0 + row) * lda + koff + cw * 8;
            CP_ASYNC16(sa + off,          Ahi + gofs);
            CP_ASYNC16(sa + ABYTES + off, Alo + gofs);
        }
        uint32_t sb = sa + 2 * ABYTES;
#pragma unroll
        for (int it = 0; it < BN / 32; it++) {
            int idx = it * 256 + tid;
            int row = idx >> 3, cw = idx & 7;
            uint32_t off = (uint32_t)(row * 128 + cw * 16);
            off ^= (off >> 3) & 0x70;
            const size_t gofs = (size_t)(n0 + row) * K + koff + cw * 8;
            CP_ASYNC16(sb + off,          Bhi + gofs);
            CP_ASYNC16(sb + BBYTES + off, Blo + gofs);
        }
    };

    float acc[4][NT][4];
#pragma unroll
    for (int mt = 0; mt < 4; mt++)
#pragma unroll
        for (int nt = 0; nt < NT; nt++)
#pragma unroll
            for (int i = 0; i < 4; i++) acc[mt][nt][i] = 0.f;

    load_stage(0, 0); CP_COMMIT();
    if (NC > 1) { load_stage(1, 1); CP_COMMIT(); }

    for (int i = 0; i < NC; i++) {
        if (i + 2 < NC) { load_stage(i + 2, (i + 2) % 3); CP_COMMIT(); }
        if (i + 2 < NC)      CP_WAIT(2);
        else if (i + 1 < NC) CP_WAIT(1);
        else                 CP_WAIT(0);
        __syncthreads();

        uint32_t sa = sbase + (i % 3) * STAGE;
        uint32_t sb = sa + 2 * ABYTES;
#pragma unroll
        for (int kk = 0; kk < 4; kk++) {
            const int cb = kk * 32 + ((lane & 16) ? 16 : 0);
            uint32_t ahi[4][4], alo[4][4];
#pragma unroll
            for (int mt = 0; mt < 4; mt++) {
                int row = wm + mt * 16 + (lane & 15);
                uint32_t off = (uint32_t)(row * 128 + cb);
                off ^= (off >> 3) & 0x70;
                LDSM4(ahi[mt][0], ahi[mt][1], ahi[mt][2], ahi[mt][3], sa + off);
                LDSM4(alo[mt][0], alo[mt][1], alo[mt][2], alo[mt][3], sa + ABYTES + off);
            }
            uint32_t bhi[NT][2], blo[NT][2];
#pragma unroll
            for (int nh = 0; nh < NT / 2; nh++) {
                int row = wn + nh * 16 + (lane & 15);
                uint32_t off = (uint32_t)(row * 128 + cb);
                off ^= (off >> 3) & 0x70;
                LDSM4(bhi[nh*2][0], bhi[nh*2+1][0], bhi[nh*2][1], bhi[nh*2+1][1], sb + off);
                LDSM4(blo[nh*2][0], blo[nh*2+1][0], blo[nh*2][1], blo[nh*2+1][1], sb + BBYTES + off);
            }
#pragma unroll
            for (int mt = 0; mt < 4; mt++)
#pragma unroll
                for (int nt = 0; nt < NT; nt++) {
                    MMA_BF16(acc[mt][nt], ahi[mt], bhi[nt]);
                    MMA_BF16(acc[mt][nt], ahi[mt], blo[nt]);
                    MMA_BF16(acc[mt][nt], alo[mt], bhi[nt]);
                }
        }
        __syncthreads();
    }

#pragma unroll
    for (int mt = 0; mt < 4; mt++) {
        int r0 = m0 + wm + mt * 16 + (lane >> 2);
#pragma unroll
        for (int nt = 0; nt < NT; nt++) {
            int c = n0 + wn + nt * 8 + (lane & 3) * 2;
            if (HILO) {
                uint32_t h0, l0, h1, l1;
                split_pack2(acc[mt][nt][0], acc[mt][nt][1], h0, l0);
                split_pack2(acc[mt][nt][2], acc[mt][nt][3], h1, l1);
                *(uint32_t*)&Chi[(size_t)r0 * N + c]       = h0;
                *(uint32_t*)&Clo[(size_t)r0 * N + c]       = l0;
                *(uint32_t*)&Chi[(size_t)(r0 + 8) * N + c] = h1;
                *(uint32_t*)&Clo[(size_t)(r0 + 8) * N + c] = l1;
            } else {
                *(float2*)&C[(size_t)r0 * N + c]       = make_float2(acc[mt][nt][0], acc[mt][nt][1]);
                *(float2*)&C[(size_t)(r0 + 8) * N + c] = make_float2(acc[mt][nt][2], acc[mt][nt][3]);
            }
        }
    }

    if (KRN) {
        if (blockIdx.x == 16) {
            // per-token ||kr||^2 (pad cols are zero, contribute nothing)
            float* red = (float*)sm;          // [128][4]
            float pr[8];
#pragma unroll
            for (int mt = 0; mt < 4; mt++) {
                float p0 = 0.f, p1 = 0.f;
#pragma unroll
                for (int nt = 0; nt < NT; nt++) {
                    p0 += acc[mt][nt][0]*acc[mt][nt][0] + acc[mt][nt][1]*acc[mt][nt][1];
                    p1 += acc[mt][nt][2]*acc[mt][nt][2] + acc[mt][nt][3]*acc[mt][nt][3];
                }
                pr[mt*2] = p0; pr[mt*2+1] = p1;
            }
#pragma unroll
            for (int i = 0; i < 8; i++) {
                pr[i] += __shfl_xor_sync(0xffffffffu, pr[i], 1);
                pr[i] += __shfl_xor_sync(0xffffffffu, pr[i], 2);
            }
            if ((lane & 3) == 0) {
#pragma unroll
                for (int i = 0; i < 8; i++) {
                    int rl = wm + (i >> 1) * 16 + (lane >> 2) + (i & 1) * 8;
                    red[rl * 4 + (warp & 3)] = pr[i];
                }
            }
            __syncthreads();
            if (tid < 128)
                g_krn[m0 + tid] = red[tid*4] + red[tid*4+1] + red[tid*4+2] + red[tid*4+3];
        }
    }
}

// ---------------- fused UKV GEMM: [kc|v] = ckv @ [W_UK|W_UV] ----------------
// bx < 16: kc head bx -> normalized k (incl. rope cols) hi/lo bf16
// bx >= 16: v head bx-16 -> transposed V hi/lo bf16 (smem-staged)
__global__ void __launch_bounds__(256) gemm_ukv(const bf16* __restrict__ Ahi,
                                                const bf16* __restrict__ Alo,
                                                const bf16* __restrict__ Bhi,
                                                const bf16* __restrict__ Blo) {
    constexpr int ABYTES = 128 * 128;
    constexpr int BBYTES = 128 * 128;
    constexpr int STAGE  = 2 * ABYTES + 2 * BBYTES;
    constexpr int NT = 4;
    constexpr int K = DCC;
    constexpr int lda = CCW;

    extern __shared__ __align__(128) char sm[];
    const uint32_t sbase = smem_u32(sm);

    const int tid  = threadIdx.x;
    const int lane = tid & 31;
    const int warp = tid >> 5;
    const int wm   = (warp >> 2) * 64;
    const int wn   = (warp & 3) * 32;
    const int m0   = blockIdx.y * 128;
    const int n0   = blockIdx.x * 128;
    const int NC   = K >> 6;

    auto load_stage = [&](int chunk, int s) {
        uint32_t sa = sbase + s * STAGE;
        const size_t koff = (size_t)chunk * 64;
#pragma unroll
        for (int it = 0; it < 4; it++) {
            int idx = it * 256 + tid;
            int row = idx >> 3, cw = idx & 7;
            uint32_t off = (uint32_t)(row * 128 + cw * 16);
            off ^= (off >> 3) & 0x70;
            const size_t gofs = (size_t)(m0 + row) * lda + koff + cw * 8;
            CP_ASYNC16(sa + off,          Ahi + gofs);
            CP_ASYNC16(sa + ABYTES + off, Alo + gofs);
        }
        uint32_t sb = sa + 2 * ABYTES;
#pragma unroll
        for (int it = 0; it < 4; it++) {
            int idx = it * 256 + tid;
            int row = idx >> 3, cw = idx & 7;
            uint32_t off = (uint32_t)(row * 128 + cw * 16);
            off ^= (off >> 3) & 0x70;
            const size_t gofs = (size_t)(n0 + row) * K + koff + cw * 8;
            CP_ASYNC16(sb + off,          Bhi + gofs);
            CP_ASYNC16(sb + BBYTES + off, Blo + gofs);
        }
    };

    float acc[4][NT][4];
#pragma unroll
    for (int mt = 0; mt < 4; mt++)
#pragma unroll
        for (int nt = 0; nt < NT; nt++)
#pragma unroll
            for (int i = 0; i < 4; i++) acc[mt][nt][i] = 0.f;

    load_stage(0, 0); CP_COMMIT();
    load_stage(1, 1); CP_COMMIT();

    for (int i = 0; i < NC; i++) {
        if (i + 2 < NC) { load_stage(i + 2, (i + 2) % 3); CP_COMMIT(); }
        if (i + 2 < NC)      CP_WAIT(2);
        else if (i + 1 < NC) CP_WAIT(1);
        else                 CP_WAIT(0);
        __syncthreads();

        uint32_t sa = sbase + (i % 3) * STAGE;
        uint32_t sb = sa + 2 * ABYTES;
#pragma unroll
        for (int kk = 0; kk < 4; kk++) {
            const int cb = kk * 32 + ((lane & 16) ? 16 : 0);
            uint32_t ahi[4][4], alo[4][4];
#pragma unroll
            for (int mt = 0; mt < 4; mt++) {
                int row = wm + mt * 16 + (lane & 15);
                uint32_t off = (uint32_t)(row * 128 + cb);
                off ^= (off >> 3) & 0x70;
                LDSM4(ahi[mt][0], ahi[mt][1], ahi[mt][2], ahi[mt][3], sa + off);
                LDSM4(alo[mt][0], alo[mt][1], alo[mt][2], alo[mt][3], sa + ABYTES + off);
            }
            uint32_t bhi[NT][2], blo[NT][2];
#pragma unroll
            for (int nh = 0; nh < NT / 2; nh++) {
                int row = wn + nh * 16 + (lane & 15);
                uint32_t off = (uint32_t)(row * 128 + cb);
                off ^= (off >> 3) & 0x70;
                LDSM4(bhi[nh*2][0], bhi[nh*2+1][0], bhi[nh*2][1], bhi[nh*2+1][1], sb + off);
                LDSM4(blo[nh*2][0], blo[nh*2+1][0], blo[nh*2][1], blo[nh*2+1][1], sb + BBYTES + off);
            }
#pragma unroll
            for (int mt = 0; mt < 4; mt++)
#pragma unroll
                for (int nt = 0; nt < NT; nt++) {
                    MMA_BF16(acc[mt][nt], ahi[mt], bhi[nt]);
                    MMA_BF16(acc[mt][nt], ahi[mt], blo[nt]);
                    MMA_BF16(acc[mt][nt], alo[mt], bhi[nt]);
                }
        }
        __syncthreads();
    }

    if (blockIdx.x < 16) {
        // ---- kc mode: normalize + rope + write k hi/lo ----
        const int h = blockIdx.x;
        float* red = (float*)sm;              // [128][4]
        float* kss = ((float*)sm) + 512;      // [128]

        float pr[8];
#pragma unroll
        for (int mt = 0; mt < 4; mt++) {
            float p0 = 0.f, p1 = 0.f;
#pragma unroll
            for (int nt = 0; nt < NT; nt++) {
                p0 += acc[mt][nt][0]*acc[mt][nt][0] + acc[mt][nt][1]*acc[mt][nt][1];
                p1 += acc[mt][nt][2]*acc[mt][nt][2] + acc[mt][nt][3]*acc[mt][nt][3];
            }
            pr[mt*2] = p0; pr[mt*2+1] = p1;
        }
#pragma unroll
        for (int i = 0; i < 8; i++) {
            pr[i] += __shfl_xor_sync(0xffffffffu, pr[i], 1);
            pr[i] += __shfl_xor_sync(0xffffffffu, pr[i], 2);
        }
        if ((lane & 3) == 0) {
#pragma unroll
            for (int i = 0; i < 8; i++) {
                int rl = wm + (i >> 1) * 16 + (lane >> 2) + (i & 1) * 8;
                red[rl * 4 + (warp & 3)] = pr[i];
            }
        }
        __syncthreads();
        if (tid < 128) {
            float n2 = red[tid*4] + red[tid*4+1] + red[tid*4+2] + red[tid*4+3]
                     + g_krn[m0 + tid];
            kss[tid] = 1.0f / fmaxf(sqrtf(n2), 1e-12f);
        }
        __syncthreads();

        // kc columns (0-127 of packed k)
#pragma unroll
        for (int mt = 0; mt < 4; mt++) {
            int rl0 = wm + mt * 16 + (lane >> 2);
            int t0 = m0 + rl0, t1 = t0 + 8;
            size_t a0 = ((size_t)((t0 >> 11) * NHH + h) * LL + (t0 & 2047)) * 192;
            size_t a1 = ((size_t)((t1 >> 11) * NHH + h) * LL + (t1 & 2047)) * 192;
            float s0f = kss[rl0], s1f = kss[rl0 + 8];
#pragma unroll
            for (int nt = 0; nt < NT; nt++) {
                int c = wn + nt * 8 + (lane & 3) * 2;
                uint32_t h0, l0w, h1, l1w;
                split_pack2(acc[mt][nt][0] * s0f, acc[mt][nt][1] * s0f, h0, l0w);
                split_pack2(acc[mt][nt][2] * s1f, acc[mt][nt][3] * s1f, h1, l1w);
                *(uint32_t*)&g_kh[a0 + c] = h0;
                *(uint32_t*)&g_kl[a0 + c] = l0w;
                *(uint32_t*)&g_kh[a1 + c] = h1;
                *(uint32_t*)&g_kl[a1 + c] = l1w;
            }
        }

        // rope columns (128-191): thread -> (token = tid>>1, 16 j's)
        {
            int tl = tid >> 1;
            int token = m0 + tl;
            int l = token & 2047;
            size_t ab = ((size_t)((token >> 11) * NHH + h) * LL + l) * 192;
            float scl = kss[tl];
#pragma unroll
            for (int jj = 0; jj < 16; jj++) {
                int j = (tid & 1) * 16 + jj;
                size_t kra = (size_t)token * CCW + 2048 + j;
                float ka = __bfloat162float(g_cc_hi[kra]) + __bfloat162float(g_cc_lo[kra]);
                float kb = __bfloat162float(g_cc_hi[kra + 32]) + __bfloat162float(g_cc_lo[kra + 32]);
                float cs = g_cos[l * 32 + j], sn = g_sin[l * 32 + j];
                float ke0 = (ka * cs - kb * sn) * scl;
                float ke1 = (kb * cs + ka * sn) * scl;
                bf16 hh, ll2;
                split_bf16(ke0, hh, ll2);
                g_kh[ab + 128 + j] = hh; g_kl[ab + 128 + j] = ll2;
                split_bf16(ke1, hh, ll2);
                g_kh[ab + 160 + j] = hh; g_kl[ab + 160 + j] = ll2;
            }
        }
    } else {
        // ---- v mode: transpose via smem, write V^T hi/lo ----
        const int h = blockIdx.x - 16;
        bf16* vsh = (bf16*)sm;                    // [128 dh][128 l]
        bf16* vsl = (bf16*)(sm + 32768);
#pragma unroll
        for (int mt = 0; mt < 4; mt++) {
            int r0 = wm + mt * 16 + (lane >> 2);
#pragma unroll
            for (int nt = 0; nt < NT; nt++) {
                int c = wn + nt * 8 + (lane & 3) * 2;
                bf16 hh, ll2;
                split_bf16(acc[mt][nt][0], hh, ll2); vsh[c*128 + r0] = hh;       vsl[c*128 + r0] = ll2;
                split_bf16(acc[mt][nt][1], hh, ll2); vsh[(c+1)*128 + r0] = hh;   vsl[(c+1)*128 + r0] = ll2;
                split_bf16(acc[mt][nt][2], hh, ll2); vsh[c*128 + r0+8] = hh;     vsl[c*128 + r0+8] = ll2;
                split_bf16(acc[mt][nt][3], hh, ll2); vsh[(c+1)*128 + r0+8] = hh; vsl[(c+1)*128 + r0+8] = ll2;
            }
        }
        __syncthreads();
        const int b  = m0 >> 11;
        const int l0 = m0 & 2047;
        const int col = tid >> 1;
        const int rh  = (tid & 1) * 64;
        size_t base = ((size_t)(b * NHH + h) * DHH + col) * LL + l0 + rh;
#pragma unroll
        for (int k2 = 0; k2 < 8; k2++) {
            *(uint4*)&g_vth[base + k2 * 8] = *(uint4*)&vsh[col * 128 + rh + k2 * 8];
            *(uint4*)&g_vtl[base + k2 * 8] = *(uint4*)&vsl[col * 128 + rh + k2 * 8];
        }
    }
}

// ---------------- pack (Q only): rope + concat + L2-normalize -> hi/lo bf16 ----------------
__global__ void __launch_bounds__(256) pack_kernel(const float* __restrict__ s_qk_ptr) {
    const int tid  = threadIdx.x;
    const int lane = tid & 31;
    const int wid  = tid >> 5;
    int flat = blockIdx.x * 8 + wid;
    const int h = flat % NHH;
    flat /= NHH;
    const int l = flat % LL;
    const int b = flat / LL;

    const int token = b * LL + l;
    const int bh    = b * NHH + h;
    const float sq  = *s_qk_ptr;

    const float cs = g_cos[l * 32 + lane];
    const float sn = g_sin[l * 32 + lane];

    float qv[4];
#pragma unroll
    for (int i = 0; i < 4; i++)
        qv[i] = g_qcqr[(size_t)token * 3072 + h * DHH + i * 32 + lane];
    float qa = g_qcqr[(size_t)token * 3072 + 2048 + h * DHRR + lane];
    float qb = g_qcqr[(size_t)token * 3072 + 2048 + h * DHRR + 32 + lane];
    float qe0 = qa * cs - qb * sn;
    float qe1 = qb * cs + qa * sn;

    float ss = qe0 * qe0 + qe1 * qe1;
#pragma unroll
    for (int i = 0; i < 4; i++) ss += qv[i] * qv[i];
#pragma unroll
    for (int off = 16; off; off >>= 1) ss += __shfl_xor_sync(0xffffffffu, ss, off);
    float qscale = sq / fmaxf(sqrtf(ss), 1e-12f);

    size_t obase = ((size_t)bh * LL + l) * 192;
    bf16 hh, ll;
#pragma unroll
    for (int i = 0; i < 4; i++) {
        split_bf16(qv[i] * qscale, hh, ll);
        g_qh[obase + i * 32 + lane] = hh;
        g_ql[obase + i * 32 + lane] = ll;
    }
    split_bf16(qe0 * qscale, hh, ll);
    g_qh[obase + 128 + lane] = hh; g_ql[obase + 128 + lane] = ll;
    split_bf16(qe1 * qscale, hh, ll);
    g_qh[obase + 160 + lane] = hh; g_ql[obase + 160 + lane] = ll;
}

// ---------------- tensor-core flash attention (bf16x3), causal ----------------
#define AT_KHI   0
#define AT_KLO   24576
#define AT_VHI   49152
#define AT_VLO   65536
#define AT_STAGE 81920
#define AT_SMEM  (2*AT_STAGE)

__global__ void __launch_bounds__(256, 1) attn_mma_kernel() {
    extern __shared__ __align__(128) char sm[];
    const uint32_t sbase = smem_u32(sm);

    const int tid  = threadIdx.x;
    const int lane = tid & 31;
    const int wid  = tid >> 5;
    const int qt   = (int)(gridDim.y - 1 - blockIdx.y);
    const int bh   = blockIdx.x;
    const int b    = bh >> 4;
    const int h    = bh & 15;

    const size_t qkbase = (size_t)bh * LL * 192;
    const size_t vbase  = (size_t)bh * DHH * LL;

    for (int i = tid; i < 128 * 24; i += 256) {
        int row = i / 24, c = i % 24;
        const size_t gofs = qkbase + (size_t)(qt * 128 + row) * 192 + c * 8;
        CP_ASYNC16(sbase + swz(row, c, 384),            g_qh + gofs);
        CP_ASYNC16(sbase + AT_STAGE + swz(row, c, 384), g_ql + gofs);
    }
    CP_COMMIT(); CP_WAIT(0);
    __syncthreads();

    uint32_t qh[12][4], ql[12][4];
#pragma unroll
    for (int ksi = 0; ksi < 12; ksi++) {
        uint32_t off = swz(wid * 16 + (lane & 15), ksi * 2 + (lane >> 4), 384);
        LDSM4(qh[ksi][0], qh[ksi][1], qh[ksi][2], qh[ksi][3], sbase + off);
        LDSM4(ql[ksi][0], ql[ksi][1], ql[ksi][2], ql[ksi][3], sbase + AT_STAGE + off);
    }
    __syncthreads();

    float o[16][4];
#pragma unroll
    for (int t = 0; t < 16; t++)
#pragma unroll
        for (int j = 0; j < 4; j++) o[t][j] = 0.f;
    float mA = -1e30f, mB = -1e30f, lA = 0.f, lB = 0.f;

    const int NTT = 2 * (qt + 1);

    auto load_tile = [&](int nt, int s) {
        uint32_t st = sbase + s * AT_STAGE;
        const int k0 = nt * 64;
        for (int i = tid; i < 64 * 24; i += 256) {
            int row = i / 24, c = i % 24;
            const size_t gofs = qkbase + (size_t)(k0 + row) * 192 + c * 8;
            CP_ASYNC16(st + AT_KHI + swz(row, c, 384), g_kh + gofs);
            CP_ASYNC16(st + AT_KLO + swz(row, c, 384), g_kl + gofs);
        }
        for (int i = tid; i < 128 * 8; i += 256) {
            int row = i >> 3, c = i & 7;
            const size_t gofs = vbase + (size_t)row * LL + k0 + c * 8;
            CP_ASYNC16(st + AT_VHI + swz(row, c, 128), g_vth + gofs);
            CP_ASYNC16(st + AT_VLO + swz(row, c, 128), g_vtl + gofs);
        }
    };

    load_tile(0, 0); CP_COMMIT();

    for (int nt = 0; nt < NTT; nt++) {
        if (nt + 1 < NTT) { load_tile(nt + 1, (nt + 1) & 1); CP_COMMIT(); CP_WAIT(1); }
        else              { CP_WAIT(0); }
        __syncthreads();

        const uint32_t st = sbase + (nt & 1) * AT_STAGE;

        float s[8][4];
#pragma unroll
        for (int t = 0; t < 8; t++)
#pragma unroll
            for (int j = 0; j < 4; j++) s[t][j] = 0.f;

#pragma unroll
        for (int ksi = 0; ksi < 12; ksi++) {
#pragma unroll
            for (int np = 0; np < 4; np++) {
                uint32_t off = swz(np * 16 + (lane & 15), ksi * 2 + (lane >> 4), 384);
                uint32_t kh0, kh1, kh2, kh3, kl0, kl1, kl2, kl3;
                LDSM4(kh0, kh1, kh2, kh3, st + AT_KHI + off);
                LDSM4(kl0, kl1, kl2, kl3, st + AT_KLO + off);
                uint32_t bhe[2] = {kh0, kh2}, bho[2] = {kh1, kh3};
                uint32_t ble[2] = {kl0, kl2}, blo2[2] = {kl1, kl3};
                MMA_BF16(s[2*np],   qh[ksi], bhe);
                MMA_BF16(s[2*np],   qh[ksi], ble);
                MMA_BF16(s[2*np],   ql[ksi], bhe);
                MMA_BF16(s[2*np+1], qh[ksi], bho);
                MMA_BF16(s[2*np+1], qh[ksi], blo2);
                MMA_BF16(s[2*np+1], ql[ksi], bho);
            }
        }

        const int rowA = qt * 128 + wid * 16 + (lane >> 2);
        if (nt * 64 + 63 > rowA) {
#pragma unroll
            for (int t = 0; t < 8; t++) {
                int col = nt * 64 + t * 8 + (lane & 3) * 2;
                if (col > rowA)         s[t][0] = -1e30f;
                if (col + 1 > rowA)     s[t][1] = -1e30f;
                if (col > rowA + 8)     s[t][2] = -1e30f;
                if (col + 1 > rowA + 8) s[t][3] = -1e30f;
            }
        }

        float mxA = -1e30f, mxB = -1e30f;
#pragma unroll
        for (int t = 0; t < 8; t++) {
            mxA = fmaxf(mxA, fmaxf(s[t][0], s[t][1]));
            mxB = fmaxf(mxB, fmaxf(s[t][2], s[t][3]));
        }
        mxA = fmaxf(mxA, __shfl_xor_sync(0xffffffffu, mxA, 1));
        mxA = fmaxf(mxA, __shfl_xor_sync(0xffffffffu, mxA, 2));
        mxB = fmaxf(mxB, __shfl_xor_sync(0xffffffffu, mxB, 1));
        mxB = fmaxf(mxB, __shfl_xor_sync(0xffffffffu, mxB, 2));

        float mnA = fmaxf(mA, mxA), mnB = fmaxf(mB, mxB);
        float scA = __expf(mA - mnA), scB = __expf(mB - mnB);
        mA = mnA; mB = mnB;

        float rsA = 0.f, rsB = 0.f;
#pragma unroll
        for (int t = 0; t < 8; t++) {
            s[t][0] = __expf(s[t][0] - mnA);
            s[t][1] = __expf(s[t][1] - mnA);
            s[t][2] = __expf(s[t][2] - mnB);
            s[t][3] = __expf(s[t][3] - mnB);
            rsA += s[t][0] + s[t][1];
            rsB += s[t][2] + s[t][3];
        }
        rsA += __shfl_xor_sync(0xffffffffu, rsA, 1);
        rsA += __shfl_xor_sync(0xffffffffu, rsA, 2);
        rsB += __shfl_xor_sync(0xffffffffu, rsB, 1);
        rsB += __shfl_xor_sync(0xffffffffu, rsB, 2);
        lA = lA * scA + rsA;
        lB = lB * scB + rsB;

#pragma unroll
        for (int t = 0; t < 16; t++) {
            o[t][0] *= scA; o[t][1] *= scA;
            o[t][2] *= scB; o[t][3] *= scB;
        }

#pragma unroll
        for (int kv = 0; kv < 4; kv++) {
            uint32_t pa_h[4], pa_l[4];
            split_pack2(s[2*kv][0],   s[2*kv][1],   pa_h[0], pa_l[0]);
            split_pack2(s[2*kv][2],   s[2*kv][3],   pa_h[1], pa_l[1]);
            split_pack2(s[2*kv+1][0], s[2*kv+1][1], pa_h[2], pa_l[2]);
            split_pack2(s[2*kv+1][2], s[2*kv+1][3], pa_h[3], pa_l[3]);
#pragma unroll
            for (int np = 0; np < 8; np++) {
                uint32_t off = swz(np * 16 + (lane & 15), kv * 2 + (lane >> 4), 128);
                uint32_t vh0, vh1, vh2, vh3, vl0, vl1, vl2, vl3;
                LDSM4(vh0, vh1, vh2, vh3, st + AT_VHI + off);
                LDSM4(vl0, vl1, vl2, vl3, st + AT_VLO + off);
                uint32_t bhe[2] = {vh0, vh2}, bho[2] = {vh1, vh3};
                uint32_t ble[2] = {vl0, vl2}, blo2[2] = {vl1, vl3};
                MMA_BF16(o[2*np],   pa_h, bhe);
                MMA_BF16(o[2*np],   pa_h, ble);
                MMA_BF16(o[2*np],   pa_l, bhe);
                MMA_BF16(o[2*np+1], pa_h, bho);
                MMA_BF16(o[2*np+1], pa_h, blo2);
                MMA_BF16(o[2*np+1], pa_l, bho);
            }
        }
        __syncthreads();
    }

    const float invA = 1.0f / lA, invB = 1.0f / lB;
    const int rowA = qt * 128 + wid * 16 + (lane >> 2);
#pragma unroll
    for (int t = 0; t < 16; t++) {
        int col = t * 8 + (lane & 3) * 2;
        size_t adrA = (size_t)(b * LL + rowA) * DD + h * DHH + col;
        size_t adrB = (size_t)(b * LL + rowA + 8) * DD + h * DHH + col;
        uint32_t hA, lA2, hB, lB2;
        split_pack2(o[t][0] * invA, o[t][1] * invA, hA, lA2);
        split_pack2(o[t][2] * invB, o[t][3] * invB, hB, lB2);
        *(uint32_t*)&g_attn_hi[adrA] = hA;
        *(uint32_t*)&g_attn_lo[adrA] = lA2;
        *(uint32_t*)&g_attn_hi[adrB] = hB;
        *(uint32_t*)&g_attn_lo[adrB] = lB2;
    }
}

// ---------------- launch ----------------
extern "C" void kernel_launch(void* const* d_in, const int* in_sizes, int n_in,
                              void* d_out, int out_size) {
    const float* x     = (const float*)d_in[0];
    const float* W_DKV = (const float*)d_in[1];
    const float* W_UK  = (const float*)d_in[2];
    const float* W_UV  = (const float*)d_in[3];
    const float* W_DQ  = (const float*)d_in[4];
    const float* W_UQ  = (const float*)d_in[5];
    const float* W_QR  = (const float*)d_in[6];
    const float* W_KR  = (const float*)d_in[7];
    const float* W_O   = (const float*)d_in[8];
    const float* s_qk  = (const float*)d_in[9];
    float* out = (float*)d_out;

    float* p_qcqr;
    cudaGetSymbolAddress((void**)&p_qcqr, g_qcqr);

    bf16 *xh, *xl, *cch, *ccl, *ah, *al;
    cudaGetSymbolAddress((void**)&xh,  g_x_hi);
    cudaGetSymbolAddress((void**)&xl,  g_x_lo);
    cudaGetSymbolAddress((void**)&cch, g_cc_hi);
    cudaGetSymbolAddress((void**)&ccl, g_cc_lo);
    cudaGetSymbolAddress((void**)&ah,  g_attn_hi);
    cudaGetSymbolAddress((void**)&al,  g_attn_lo);

    bf16 *wdkdqh, *wdkdql, *wukvh, *wukvl, *wuqqrh, *wuqqrl, *woh, *wol;
    cudaGetSymbolAddress((void**)&wdkdqh, g_wdkdq_hi);
    cudaGetSymbolAddress((void**)&wdkdql, g_wdkdq_lo);
    cudaGetSymbolAddress((void**)&wukvh,  g_wukv_hi);
    cudaGetSymbolAddress((void**)&wukvl,  g_wukv_lo);
    cudaGetSymbolAddress((void**)&wuqqrh, g_wuqqr_hi);
    cudaGetSymbolAddress((void**)&wuqqrl, g_wuqqr_lo);
    cudaGetSymbolAddress((void**)&woh,    g_wo_hi);
    cudaGetSymbolAddress((void**)&wol,    g_wo_lo);

    rope_table_kernel<<<(LL*32 + 255) / 256, 256>>>();

    cudaMemsetAsync(wdkdqh + (size_t)2112 * 2048, 0, (size_t)64 * 2048 * sizeof(bf16));
    cudaMemsetAsync(wdkdql + (size_t)2112 * 2048, 0, (size_t)64 * 2048 * sizeof(bf16));

    dim3 tb(32, 8);
    transpose_conv<<<dim3(DCC/32,  DD/32),  tb>>>(W_DKV, wdkdqh,                     wdkdql,                     DD,  DCC);
    transpose_conv<<<dim3(DCC/32,  DD/32),  tb>>>(W_DQ,  wdkdqh + (size_t)1024*2048, wdkdql + (size_t)1024*2048, DD,  DCC);
    transpose_conv<<<dim3(DHRR/32, DD/32),  tb>>>(W_KR,  wdkdqh + (size_t)2048*2048, wdkdql + (size_t)2048*2048, DD,  DHRR);
    transpose_conv<<<dim3(DD/32,   DCC/32), tb>>>(W_UK,  wukvh,                      wukvl,                      DCC, DD);
    transpose_conv<<<dim3(DD/32,   DCC/32), tb>>>(W_UV,  wukvh + (size_t)2048*1024,  wukvl + (size_t)2048*1024,  DCC, DD);
    transpose_conv<<<dim3(DD/32,   DCC/32), tb>>>(W_UQ,  wuqqrh,                     wuqqrl,                     DCC, DD);
    transpose_conv<<<dim3(DCC/32,  DCC/32), tb>>>(W_QR,  wuqqrh + (size_t)2048*1024, wuqqrl + (size_t)2048*1024, DCC, DCC);
    transpose_conv<<<dim3(DD/32,   DD/32),  tb>>>(W_O,   woh,                        wol,                        DD,  DD);

    constexpr int SMEM128 = 3 * (2*128*128 + 2*128*128);  // 196608
    cudaFuncSetAttribute((const void*)gemm_bf16x3<128,true,true>,   cudaFuncAttributeMaxDynamicSharedMemorySize, SMEM128);
    cudaFuncSetAttribute((const void*)gemm_bf16x3<128,false,false>, cudaFuncAttributeMaxDynamicSharedMemorySize, SMEM128);
    cudaFuncSetAttribute((const void*)gemm_ukv,                     cudaFuncAttributeMaxDynamicSharedMemorySize, SMEM128);

    // x -> hi/lo
    conv_hilo<<<(MTOK*DD/4 + 255) / 256, 256>>>(x, xh, xl, MTOK*DD/4);

    // fused down projections: [ckv | cq | kr | pad], + per-token ||kr||^2
    gemm_bf16x3<128,true,true><<<dim3(CCW/128, MTOK/128), 256, SMEM128>>>(
        xh, xl, DD, wdkdqh, wdkdql, nullptr, cch, ccl, CCW, DD);

    // fused up projection K/V: kc tiles -> normalized k (+rope), v tiles -> V^T
    gemm_ukv<<<dim3(32, MTOK/128), 256, SMEM128>>>(cch, ccl, wukvh, wukvl);

    // [qc | qr] = cq @ [W_UQ | W_QR]
    gemm_bf16x3<128,false,false><<<dim3(3072/128, MTOK/128), 256, SMEM128>>>(
        cch + 1024, ccl + 1024, CCW, wuqqrh, wuqqrl, p_qcqr, nullptr, nullptr, 3072, DCC);

    // pack q (hi/lo bf16)
    pack_kernel<<<(BB*LL*NHH)/8, 256>>>(s_qk);

    // tensor-core flash attention (heavy q-tiles first)
    cudaFuncSetAttribute(attn_mma_kernel, cudaFuncAttributeMaxDynamicSharedMemorySize, AT_SMEM);
    attn_mma_kernel<<<dim3(BHT, LL/128), 256, AT_SMEM>>>();

    // output projection
    gemm_bf16x3<128,false,false><<<dim3(DD/128, MTOK/128), 256, SMEM128>>>(
        ah, al, DD, woh, wol, out, nullptr, nullptr, DD, DD);
}

// round 9
// speedup vs baseline: 1.0486x; 1.0486x over previous
#include <cuda_runtime.h>
#include <cuda_bf16.h>
#include <math.h>
#include <stdint.h>

// Problem constants
#define BB    4
#define LL    2048
#define DD    2048
#define NHH   16
#define DHH   128
#define DHRR  64
#define DCC   1024
#define MTOK  (BB*LL)          // 8192
#define BHT   (BB*NHH)         // 64
#define CCW   2176             // ckv(1024) | cq(1024) | kr(64) | pad(64)

typedef __nv_bfloat16 bf16;

// ---------------- device scratch (static, no allocation) ----------------
__device__ float g_kcvt [MTOK*4096];        // kc | vt   (cols 0-2047 | 2048-4095)
__device__ float g_qcqr [MTOK*3072];        // qc | qr   (cols 0-2047 | 2048-3071)
__device__ float g_cos  [LL*32];
__device__ float g_sin  [LL*32];

// packed q/k (bh, l, 192) hi/lo bf16; V^T (bh, dh128, l) hi/lo bf16
__device__ bf16 g_qh [BHT*LL*192];
__device__ bf16 g_ql [BHT*LL*192];
__device__ bf16 g_kh [BHT*LL*192];
__device__ bf16 g_kl [BHT*LL*192];
__device__ bf16 g_vth[BHT*DHH*LL];
__device__ bf16 g_vtl[BHT*DHH*LL];

// A-side activations, hi/lo bf16
__device__ bf16 g_x_hi   [MTOK*DD];
__device__ bf16 g_x_lo   [MTOK*DD];
__device__ bf16 g_cc_hi  [MTOK*CCW];        // ckv | cq | kr | pad
__device__ bf16 g_cc_lo  [MTOK*CCW];
__device__ bf16 g_attn_hi[MTOK*DD];
__device__ bf16 g_attn_lo[MTOK*DD];

// B-side weights, transposed to K-major [N,K], hi/lo bf16, N-concatenated
__device__ bf16 g_wdkdq_hi[CCW*2048],  g_wdkdq_lo[CCW*2048];   // DKV^T | DQ^T | KR^T | pad
__device__ bf16 g_wukv_hi [4096*1024], g_wukv_lo [4096*1024];  // UK^T | UV^T
__device__ bf16 g_wuqqr_hi[3072*1024], g_wuqqr_lo[3072*1024];  // UQ^T | QR^T
__device__ bf16 g_wo_hi   [DD*DD],     g_wo_lo   [DD*DD];

// ---------------- helpers ----------------
__device__ __forceinline__ uint32_t smem_u32(const void* p) {
    uint32_t a;
    asm("{ .reg .u64 t; cvta.to.shared.u64 t, %1; cvt.u32.u64 %0, t; }" : "=r"(a) : "l"(p));
    return a;
}

#define CP_ASYNC16(dst, src) \
    asm volatile("cp.async.cg.shared.global [%0], [%1], 16;" :: "r"(dst), "l"(src))
#define CP_COMMIT() asm volatile("cp.async.commit_group;" ::: "memory")
#define CP_WAIT(n)  asm volatile("cp.async.wait_group %0;" :: "n"(n) : "memory")

#define LDSM4(r0, r1, r2, r3, addr) \
    asm volatile("ldmatrix.sync.aligned.m8n8.x4.shared.b16 {%0,%1,%2,%3}, [%4];" \
                 : "=r"(r0), "=r"(r1), "=r"(r2), "=r"(r3) : "r"(addr))

#define MMA_BF16(c, a, b) \
    asm volatile("mma.sync.aligned.m16n8k16.row.col.f32.bf16.bf16.f32 " \
                 "{%0,%1,%2,%3}, {%4,%5,%6,%7}, {%8,%9}, {%0,%1,%2,%3};" \
                 : "+f"((c)[0]), "+f"((c)[1]), "+f"((c)[2]), "+f"((c)[3]) \
                 : "r"((a)[0]), "r"((a)[1]), "r"((a)[2]), "r"((a)[3]), \
                   "r"((b)[0]), "r"((b)[1]))

__device__ __forceinline__ void split_bf16(float x, bf16& hi, bf16& lo) {
    hi = __float2bfloat16_rn(x);
    lo = __float2bfloat16_rn(x - __bfloat162float(hi));
}
__device__ __forceinline__ uint16_t bfb(bf16 v) { return *(uint16_t*)&v; }

__device__ __forceinline__ void split_pack2(float x, float y, uint32_t& hi, uint32_t& lo) {
    bf16 hx, lx, hy, ly;
    split_bf16(x, hx, lx);
    split_bf16(y, hy, ly);
    hi = ((uint32_t)bfb(hy) << 16) | bfb(hx);
    lo = ((uint32_t)bfb(ly) << 16) | bfb(lx);
}

__device__ __forceinline__ uint32_t swz(int row, int c, int rowbytes) {
    int c2 = (c & ~7) | ((c ^ row) & 7);
    return (uint32_t)(row * rowbytes + c2 * 16);
}

// ---------------- rope tables ----------------
__global__ void rope_table_kernel() {
    int i = blockIdx.x * blockDim.x + threadIdx.x;
    if (i >= LL*32) return;
    int l = i >> 5;
    int j = i & 31;
    double invf = pow(10000.0, -(double)j / 32.0);
    double ang  = (double)l * invf;
    g_cos[i] = (float)cos(ang);
    g_sin[i] = (float)sin(ang);
}

// ---------------- convert fp32 -> hi/lo bf16 ----------------
__global__ void __launch_bounds__(256) conv_hilo(const float* __restrict__ in,
                                                 bf16* __restrict__ hi,
                                                 bf16* __restrict__ lo, int n4) {
    int i = blockIdx.x * blockDim.x + threadIdx.x;
    if (i >= n4) return;
    float4 v = *(const float4*)&in[(size_t)i * 4];
    bf16 h[4], l[4];
    split_bf16(v.x, h[0], l[0]);
    split_bf16(v.y, h[1], l[1]);
    split_bf16(v.z, h[2], l[2]);
    split_bf16(v.w, h[3], l[3]);
    *(uint64_t*)&hi[(size_t)i * 4] = *(uint64_t*)h;
    *(uint64_t*)&lo[(size_t)i * 4] = *(uint64_t*)l;
}

// ---------------- transpose + convert: out[C][R] (hi/lo bf16) = in[R][C] ----------------
__global__ void __launch_bounds__(256) transpose_conv(const float* __restrict__ in,
                                                      bf16* __restrict__ out_hi,
                                                      bf16* __restrict__ out_lo,
                                                      int R, int C) {
    __shared__ float t[32][33];
    int bx = blockIdx.x * 32, by = blockIdx.y * 32;
    int tx = threadIdx.x, ty = threadIdx.y;     // (32, 8)
    int x = bx + tx;
#pragma unroll
    for (int j = 0; j < 32; j += 8)
        t[ty + j][tx] = in[(size_t)(by + ty + j) * C + x];
    __syncthreads();
    int xo = by + tx;
#pragma unroll
    for (int j = 0; j < 32; j += 8) {
        float v = t[tx][ty + j];
        bf16 h, l;
        split_bf16(v, h, l);
        size_t o = (size_t)(bx + ty + j) * R + xo;
        out_hi[o] = h;
        out_lo[o] = l;
    }
}

// ---------------- per-head V transpose: g_kcvt cols 2048+ -> (bh, dh, l) hi/lo ----------------
__global__ void __launch_bounds__(256) v_transpose_kernel() {
    __shared__ float t[32][33];
    int dh0 = blockIdx.x * 32;
    int l0  = blockIdx.y * 32;
    int bh  = blockIdx.z;
    int b = bh >> 4, h = bh & 15;
    int tx = threadIdx.x, ty = threadIdx.y;   // (32, 8)
#pragma unroll
    for (int j = 0; j < 32; j += 8)
        t[ty + j][tx] = g_kcvt[(size_t)(b * LL + l0 + ty + j) * 4096 + 2048 + h * DHH + dh0 + tx];
    __syncthreads();
#pragma unroll
    for (int j = 0; j < 32; j += 8) {
        float v = t[tx][ty + j];
        bf16 hh, ll;
        split_bf16(v, hh, ll);
        size_t o = (size_t)bh * DHH * LL + (size_t)(dh0 + ty + j) * LL + l0 + tx;
        g_vth[o] = hh;
        g_vtl[o] = ll;
    }
}

// ---------------- bf16x3 mma.sync GEMM: C[M,N] = A[M,K] @ BT[N,K]^T ----------------
// CTA tile 128 x BN, NS-stage cp.async pipeline.
template<int BN, int NS, bool HILO>
__global__ void __launch_bounds__(256) gemm_bf16x3(const bf16* __restrict__ Ahi,
                                                   const bf16* __restrict__ Alo,
                                                   int lda,
                                                   const bf16* __restrict__ Bhi,
                                                   const bf16* __restrict__ Blo,
                                                   float* __restrict__ C,
                                                   bf16* __restrict__ Chi,
                                                   bf16* __restrict__ Clo,
                                                   int N, int K) {
    constexpr int ABYTES = 128 * 128;
    constexpr int BBYTES = BN * 128;
    constexpr int STAGE  = 2 * ABYTES + 2 * BBYTES;
    constexpr int WN = BN / 4;
    constexpr int NT = WN / 8;

    extern __shared__ __align__(128) char sm[];
    const uint32_t sbase = smem_u32(sm);

    const int tid  = threadIdx.x;
    const int lane = tid & 31;
    const int warp = tid >> 5;
    const int wm   = (warp >> 2) * 64;
    const int wn   = (warp & 3) * WN;
    const int m0   = blockIdx.y * 128;
    const int n0   = blockIdx.x * BN;
    const int NC   = K >> 6;

    auto load_stage = [&](int chunk, int s) {
        uint32_t sa = sbase + s * STAGE;
        const size_t koff = (size_t)chunk * 64;
#pragma unroll
        for (int it = 0; it < 4; it++) {
            int idx = it * 256 + tid;
            int row = idx >> 3, cw = idx & 7;
            uint32_t off = (uint32_t)(row * 128 + cw * 16);
            off ^= (off >> 3) & 0x70;
            const size_t gofs = (size_t)(m0 + row) * lda + koff + cw * 8;
            CP_ASYNC16(sa + off,          Ahi + gofs);
            CP_ASYNC16(sa + ABYTES + off, Alo + gofs);
        }
        uint32_t sb = sa + 2 * ABYTES;
#pragma unroll
        for (int it = 0; it < BN / 32; it++) {
            int idx = it * 256 + tid;
            int row = idx >> 3, cw = idx & 7;
            uint32_t off = (uint32_t)(row * 128 + cw * 16);
            off ^= (off >> 3) & 0x70;
            const size_t gofs = (size_t)(n0 + row) * K + koff + cw * 8;
            CP_ASYNC16(sb + off,          Bhi + gofs);
            CP_ASYNC16(sb + BBYTES + off, Blo + gofs);
        }
    };

    float acc[4][NT][4];
#pragma unroll
    for (int mt = 0; mt < 4; mt++)
#pragma unroll
        for (int nt = 0; nt < NT; nt++)
#pragma unroll
            for (int i = 0; i < 4; i++) acc[mt][nt][i] = 0.f;

    load_stage(0, 0); CP_COMMIT();
    if (NS == 3 && NC > 1) { load_stage(1, 1); CP_COMMIT(); }

    for (int i = 0; i < NC; i++) {
        if (i + NS - 1 < NC) { load_stage(i + NS - 1, (i + NS - 1) % NS); CP_COMMIT(); }
        if (NS == 3) {
            if (i + 2 < NC)      CP_WAIT(2);
            else if (i + 1 < NC) CP_WAIT(1);
            else                 CP_WAIT(0);
        } else {
            if (i + 1 < NC)      CP_WAIT(1);
            else                 CP_WAIT(0);
        }
        __syncthreads();

        uint32_t sa = sbase + (i % NS) * STAGE;
        uint32_t sb = sa + 2 * ABYTES;
#pragma unroll
        for (int kk = 0; kk < 4; kk++) {
            const int cb = kk * 32 + ((lane & 16) ? 16 : 0);
            uint32_t ahi[4][4], alo[4][4];
#pragma unroll
            for (int mt = 0; mt < 4; mt++) {
                int row = wm + mt * 16 + (lane & 15);
                uint32_t off = (uint32_t)(row * 128 + cb);
                off ^= (off >> 3) & 0x70;
                LDSM4(ahi[mt][0], ahi[mt][1], ahi[mt][2], ahi[mt][3], sa + off);
                LDSM4(alo[mt][0], alo[mt][1], alo[mt][2], alo[mt][3], sa + ABYTES + off);
            }
            uint32_t bhi[NT][2], blo[NT][2];
#pragma unroll
            for (int nh = 0; nh < NT / 2; nh++) {
                int row = wn + nh * 16 + (lane & 15);
                uint32_t off = (uint32_t)(row * 128 + cb);
                off ^= (off >> 3) & 0x70;
                LDSM4(bhi[nh*2][0], bhi[nh*2+1][0], bhi[nh*2][1], bhi[nh*2+1][1], sb + off);
                LDSM4(blo[nh*2][0], blo[nh*2+1][0], blo[nh*2][1], blo[nh*2+1][1], sb + BBYTES + off);
            }
#pragma unroll
            for (int mt = 0; mt < 4; mt++)
#pragma unroll
                for (int nt = 0; nt < NT; nt++) {
                    MMA_BF16(acc[mt][nt], ahi[mt], bhi[nt]);
                    MMA_BF16(acc[mt][nt], ahi[mt], blo[nt]);
                    MMA_BF16(acc[mt][nt], alo[mt], bhi[nt]);
                }
        }
        __syncthreads();
    }

#pragma unroll
    for (int mt = 0; mt < 4; mt++) {
        int r0 = m0 + wm + mt * 16 + (lane >> 2);
#pragma unroll
        for (int nt = 0; nt < NT; nt++) {
            int c = n0 + wn + nt * 8 + (lane & 3) * 2;
            if (HILO) {
                uint32_t h0, l0, h1, l1;
                split_pack2(acc[mt][nt][0], acc[mt][nt][1], h0, l0);
                split_pack2(acc[mt][nt][2], acc[mt][nt][3], h1, l1);
                *(uint32_t*)&Chi[(size_t)r0 * N + c]       = h0;
                *(uint32_t*)&Clo[(size_t)r0 * N + c]       = l0;
                *(uint32_t*)&Chi[(size_t)(r0 + 8) * N + c] = h1;
                *(uint32_t*)&Clo[(size_t)(r0 + 8) * N + c] = l1;
            } else {
                *(float2*)&C[(size_t)r0 * N + c]       = make_float2(acc[mt][nt][0], acc[mt][nt][1]);
                *(float2*)&C[(size_t)(r0 + 8) * N + c] = make_float2(acc[mt][nt][2], acc[mt][nt][3]);
            }
        }
    }
}

// ---------------- pack: rope + concat + L2-normalize -> hi/lo bf16 ----------------
__global__ void __launch_bounds__(256) pack_kernel(const float* __restrict__ s_qk_ptr) {
    const int tid  = threadIdx.x;
    const int lane = tid & 31;
    const int wid  = tid >> 5;
    int flat = blockIdx.x * 8 + wid;
    const int h = flat % NHH;
    flat /= NHH;
    const int l = flat % LL;
    const int b = flat / LL;

    const int token = b * LL + l;
    const int bh    = b * NHH + h;
    const float sq  = *s_qk_ptr;

    const float cs = g_cos[l * 32 + lane];
    const float sn = g_sin[l * 32 + lane];

    float qv[4];
#pragma unroll
    for (int i = 0; i < 4; i++)
        qv[i] = g_qcqr[(size_t)token * 3072 + h * DHH + i * 32 + lane];
    float qa = g_qcqr[(size_t)token * 3072 + 2048 + h * DHRR + lane];
    float qb = g_qcqr[(size_t)token * 3072 + 2048 + h * DHRR + 32 + lane];
    float qe0 = qa * cs - qb * sn;
    float qe1 = qb * cs + qa * sn;

    float ss = qe0 * qe0 + qe1 * qe1;
#pragma unroll
    for (int i = 0; i < 4; i++) ss += qv[i] * qv[i];
#pragma unroll
    for (int off = 16; off; off >>= 1) ss += __shfl_xor_sync(0xffffffffu, ss, off);
    float qscale = sq / fmaxf(sqrtf(ss), 1e-12f);

    size_t obase = ((size_t)bh * LL + l) * 192;
    bf16 hh, ll;
#pragma unroll
    for (int i = 0; i < 4; i++) {
        split_bf16(qv[i] * qscale, hh, ll);
        g_qh[obase + i * 32 + lane] = hh;
        g_ql[obase + i * 32 + lane] = ll;
    }
    split_bf16(qe0 * qscale, hh, ll);
    g_qh[obase + 128 + lane] = hh; g_ql[obase + 128 + lane] = ll;
    split_bf16(qe1 * qscale, hh, ll);
    g_qh[obase + 160 + lane] = hh; g_ql[obase + 160 + lane] = ll;

    float kv[4];
#pragma unroll
    for (int i = 0; i < 4; i++)
        kv[i] = g_kcvt[(size_t)token * 4096 + h * DHH + i * 32 + lane];
    // k_rope latent from fused down-proj (hi+lo reconstruction)
    float ka = __bfloat162float(g_cc_hi[(size_t)token * CCW + 2048 + lane]) +
               __bfloat162float(g_cc_lo[(size_t)token * CCW + 2048 + lane]);
    float kb = __bfloat162float(g_cc_hi[(size_t)token * CCW + 2048 + 32 + lane]) +
               __bfloat162float(g_cc_lo[(size_t)token * CCW + 2048 + 32 + lane]);
    float ke0 = ka * cs - kb * sn;
    float ke1 = kb * cs + ka * sn;

    float ks = ke0 * ke0 + ke1 * ke1;
#pragma unroll
    for (int i = 0; i < 4; i++) ks += kv[i] * kv[i];
#pragma unroll
    for (int off = 16; off; off >>= 1) ks += __shfl_xor_sync(0xffffffffu, ks, off);
    float kscale = 1.0f / fmaxf(sqrtf(ks), 1e-12f);

#pragma unroll
    for (int i = 0; i < 4; i++) {
        split_bf16(kv[i] * kscale, hh, ll);
        g_kh[obase + i * 32 + lane] = hh;
        g_kl[obase + i * 32 + lane] = ll;
    }
    split_bf16(ke0 * kscale, hh, ll);
    g_kh[obase + 128 + lane] = hh; g_kl[obase + 128 + lane] = ll;
    split_bf16(ke1 * kscale, hh, ll);
    g_kh[obase + 160 + lane] = hh; g_kl[obase + 160 + lane] = ll;
}

// ---------------- tensor-core flash attention (bf16x3), causal ----------------
#define AT_KHI   0
#define AT_KLO   24576
#define AT_VHI   49152
#define AT_VLO   65536
#define AT_STAGE 81920
#define AT_SMEM  (2*AT_STAGE)

__global__ void __launch_bounds__(256, 1) attn_mma_kernel() {
    extern __shared__ __align__(128) char sm[];
    const uint32_t sbase = smem_u32(sm);

    const int tid  = threadIdx.x;
    const int lane = tid & 31;
    const int wid  = tid >> 5;
    const int qt   = (int)(gridDim.y - 1 - blockIdx.y);
    const int bh   = blockIdx.x;
    const int b    = bh >> 4;
    const int h    = bh & 15;

    const size_t qkbase = (size_t)bh * LL * 192;
    const size_t vbase  = (size_t)bh * DHH * LL;

    for (int i = tid; i < 128 * 24; i += 256) {
        int row = i / 24, c = i % 24;
        const size_t gofs = qkbase + (size_t)(qt * 128 + row) * 192 + c * 8;
        CP_ASYNC16(sbase + swz(row, c, 384),            g_qh + gofs);
        CP_ASYNC16(sbase + AT_STAGE + swz(row, c, 384), g_ql + gofs);
    }
    CP_COMMIT(); CP_WAIT(0);
    __syncthreads();

    uint32_t qh[12][4], ql[12][4];
#pragma unroll
    for (int ksi = 0; ksi < 12; ksi++) {
        uint32_t off = swz(wid * 16 + (lane & 15), ksi * 2 + (lane >> 4), 384);
        LDSM4(qh[ksi][0], qh[ksi][1], qh[ksi][2], qh[ksi][3], sbase + off);
        LDSM4(ql[ksi][0], ql[ksi][1], ql[ksi][2], ql[ksi][3], sbase + AT_STAGE + off);
    }
    __syncthreads();

    float o[16][4];
#pragma unroll
    for (int t = 0; t < 16; t++)
#pragma unroll
        for (int j = 0; j < 4; j++) o[t][j] = 0.f;
    float mA = -1e30f, mB = -1e30f, lA = 0.f, lB = 0.f;

    const int NTT = 2 * (qt + 1);

    auto load_tile = [&](int nt, int s) {
        uint32_t st = sbase + s * AT_STAGE;
        const int k0 = nt * 64;
        for (int i = tid; i < 64 * 24; i += 256) {
            int row = i / 24, c = i % 24;
            const size_t gofs = qkbase + (size_t)(k0 + row) * 192 + c * 8;
            CP_ASYNC16(st + AT_KHI + swz(row, c, 384), g_kh + gofs);
            CP_ASYNC16(st + AT_KLO + swz(row, c, 384), g_kl + gofs);
        }
        for (int i = tid; i < 128 * 8; i += 256) {
            int row = i >> 3, c = i & 7;
            const size_t gofs = vbase + (size_t)row * LL + k0 + c * 8;
            CP_ASYNC16(st + AT_VHI + swz(row, c, 128), g_vth + gofs);
            CP_ASYNC16(st + AT_VLO + swz(row, c, 128), g_vtl + gofs);
        }
    };

    load_tile(0, 0); CP_COMMIT();

    for (int nt = 0; nt < NTT; nt++) {
        if (nt + 1 < NTT) { load_tile(nt + 1, (nt + 1) & 1); CP_COMMIT(); CP_WAIT(1); }
        else              { CP_WAIT(0); }
        __syncthreads();

        const uint32_t st = sbase + (nt & 1) * AT_STAGE;

        float s[8][4];
#pragma unroll
        for (int t = 0; t < 8; t++)
#pragma unroll
            for (int j = 0; j < 4; j++) s[t][j] = 0.f;

#pragma unroll
        for (int ksi = 0; ksi < 12; ksi++) {
#pragma unroll
            for (int np = 0; np < 4; np++) {
                uint32_t off = swz(np * 16 + (lane & 15), ksi * 2 + (lane >> 4), 384);
                uint32_t kh0, kh1, kh2, kh3, kl0, kl1, kl2, kl3;
                LDSM4(kh0, kh1, kh2, kh3, st + AT_KHI + off);
                LDSM4(kl0, kl1, kl2, kl3, st + AT_KLO + off);
                uint32_t bhe[2] = {kh0, kh2}, bho[2] = {kh1, kh3};
                uint32_t ble[2] = {kl0, kl2}, blo2[2] = {kl1, kl3};
                MMA_BF16(s[2*np],   qh[ksi], bhe);
                MMA_BF16(s[2*np],   qh[ksi], ble);
                MMA_BF16(s[2*np],   ql[ksi], bhe);
                MMA_BF16(s[2*np+1], qh[ksi], bho);
                MMA_BF16(s[2*np+1], qh[ksi], blo2);
                MMA_BF16(s[2*np+1], ql[ksi], bho);
            }
        }

        const int rowA = qt * 128 + wid * 16 + (lane >> 2);
        if (nt * 64 + 63 > rowA) {
#pragma unroll
            for (int t = 0; t < 8; t++) {
                int col = nt * 64 + t * 8 + (lane & 3) * 2;
                if (col > rowA)         s[t][0] = -1e30f;
                if (col + 1 > rowA)     s[t][1] = -1e30f;
                if (col > rowA + 8)     s[t][2] = -1e30f;
                if (col + 1 > rowA + 8) s[t][3] = -1e30f;
            }
        }

        float mxA = -1e30f, mxB = -1e30f;
#pragma unroll
        for (int t = 0; t < 8; t++) {
            mxA = fmaxf(mxA, fmaxf(s[t][0], s[t][1]));
            mxB = fmaxf(mxB, fmaxf(s[t][2], s[t][3]));
        }
        mxA = fmaxf(mxA, __shfl_xor_sync(0xffffffffu, mxA, 1));
        mxA = fmaxf(mxA, __shfl_xor_sync(0xffffffffu, mxA, 2));
        mxB = fmaxf(mxB, __shfl_xor_sync(0xffffffffu, mxB, 1));
        mxB = fmaxf(mxB, __shfl_xor_sync(0xffffffffu, mxB, 2));

        float mnA = fmaxf(mA, mxA), mnB = fmaxf(mB, mxB);
        float scA = __expf(mA - mnA), scB = __expf(mB - mnB);
        mA = mnA; mB = mnB;

        float rsA = 0.f, rsB = 0.f;
#pragma unroll
        for (int t = 0; t < 8; t++) {
            s[t][0] = __expf(s[t][0] - mnA);
            s[t][1] = __expf(s[t][1] - mnA);
            s[t][2] = __expf(s[t][2] - mnB);
            s[t][3] = __expf(s[t][3] - mnB);
            rsA += s[t][0] + s[t][1];
            rsB += s[t][2] + s[t][3];
        }
        rsA += __shfl_xor_sync(0xffffffffu, rsA, 1);
        rsA += __shfl_xor_sync(0xffffffffu, rsA, 2);
        rsB += __shfl_xor_sync(0xffffffffu, rsB, 1);
        rsB += __shfl_xor_sync(0xffffffffu, rsB, 2);
        lA = lA * scA + rsA;
        lB = lB * scB + rsB;

#pragma unroll
        for (int t = 0; t < 16; t++) {
            o[t][0] *= scA; o[t][1] *= scA;
            o[t][2] *= scB; o[t][3] *= scB;
        }

#pragma unroll
        for (int kv = 0; kv < 4; kv++) {
            uint32_t pa_h[4], pa_l[4];
            split_pack2(s[2*kv][0],   s[2*kv][1],   pa_h[0], pa_l[0]);
            split_pack2(s[2*kv][2],   s[2*kv][3],   pa_h[1], pa_l[1]);
            split_pack2(s[2*kv+1][0], s[2*kv+1][1], pa_h[2], pa_l[2]);
            split_pack2(s[2*kv+1][2], s[2*kv+1][3], pa_h[3], pa_l[3]);
#pragma unroll
            for (int np = 0; np < 8; np++) {
                uint32_t off = swz(np * 16 + (lane & 15), kv * 2 + (lane >> 4), 128);
                uint32_t vh0, vh1, vh2, vh3, vl0, vl1, vl2, vl3;
                LDSM4(vh0, vh1, vh2, vh3, st + AT_VHI + off);
                LDSM4(vl0, vl1, vl2, vl3, st + AT_VLO + off);
                uint32_t bhe[2] = {vh0, vh2}, bho[2] = {vh1, vh3};
                uint32_t ble[2] = {vl0, vl2}, blo2[2] = {vl1, vl3};
                MMA_BF16(o[2*np],   pa_h, bhe);
                MMA_BF16(o[2*np],   pa_h, ble);
                MMA_BF16(o[2*np],   pa_l, bhe);
                MMA_BF16(o[2*np+1], pa_h, bho);
                MMA_BF16(o[2*np+1], pa_h, blo2);
                MMA_BF16(o[2*np+1], pa_l, bho);
            }
        }
        __syncthreads();
    }

    const float invA = 1.0f / lA, invB = 1.0f / lB;
    const int rowA = qt * 128 + wid * 16 + (lane >> 2);
#pragma unroll
    for (int t = 0; t < 16; t++) {
        int col = t * 8 + (lane & 3) * 2;
        size_t adrA = (size_t)(b * LL + rowA) * DD + h * DHH + col;
        size_t adrB = (size_t)(b * LL + rowA + 8) * DD + h * DHH + col;
        uint32_t hA, lA2, hB, lB2;
        split_pack2(o[t][0] * invA, o[t][1] * invA, hA, lA2);
        split_pack2(o[t][2] * invB, o[t][3] * invB, hB, lB2);
        *(uint32_t*)&g_attn_hi[adrA] = hA;
        *(uint32_t*)&g_attn_lo[adrA] = lA2;
        *(uint32_t*)&g_attn_hi[adrB] = hB;
        *(uint32_t*)&g_attn_lo[adrB] = lB2;
    }
}

// ---------------- launch ----------------
extern "C" void kernel_launch(void* const* d_in, const int* in_sizes, int n_in,
                              void* d_out, int out_size) {
    const float* x     = (const float*)d_in[0];
    const float* W_DKV = (const float*)d_in[1];
    const float* W_UK  = (const float*)d_in[2];
    const float* W_UV  = (const float*)d_in[3];
    const float* W_DQ  = (const float*)d_in[4];
    const float* W_UQ  = (const float*)d_in[5];
    const float* W_QR  = (const float*)d_in[6];
    const float* W_KR  = (const float*)d_in[7];
    const float* W_O   = (const float*)d_in[8];
    const float* s_qk  = (const float*)d_in[9];
    float* out = (float*)d_out;

    float *p_kcvt, *p_qcqr;
    cudaGetSymbolAddress((void**)&p_kcvt, g_kcvt);
    cudaGetSymbolAddress((void**)&p_qcqr, g_qcqr);

    bf16 *xh, *xl, *cch, *ccl, *ah, *al;
    cudaGetSymbolAddress((void**)&xh,  g_x_hi);
    cudaGetSymbolAddress((void**)&xl,  g_x_lo);
    cudaGetSymbolAddress((void**)&cch, g_cc_hi);
    cudaGetSymbolAddress((void**)&ccl, g_cc_lo);
    cudaGetSymbolAddress((void**)&ah,  g_attn_hi);
    cudaGetSymbolAddress((void**)&al,  g_attn_lo);

    bf16 *wdkdqh, *wdkdql, *wukvh, *wukvl, *wuqqrh, *wuqqrl, *woh, *wol;
    cudaGetSymbolAddress((void**)&wdkdqh, g_wdkdq_hi);
    cudaGetSymbolAddress((void**)&wdkdql, g_wdkdq_lo);
    cudaGetSymbolAddress((void**)&wukvh,  g_wukv_hi);
    cudaGetSymbolAddress((void**)&wukvl,  g_wukv_lo);
    cudaGetSymbolAddress((void**)&wuqqrh, g_wuqqr_hi);
    cudaGetSymbolAddress((void**)&wuqqrl, g_wuqqr_lo);
    cudaGetSymbolAddress((void**)&woh,    g_wo_hi);
    cudaGetSymbolAddress((void**)&wol,    g_wo_lo);

    rope_table_kernel<<<(LL*32 + 255) / 256, 256>>>();

    cudaMemsetAsync(wdkdqh + (size_t)2112 * 2048, 0, (size_t)64 * 2048 * sizeof(bf16));
    cudaMemsetAsync(wdkdql + (size_t)2112 * 2048, 0, (size_t)64 * 2048 * sizeof(bf16));

    dim3 tb(32, 8);
    transpose_conv<<<dim3(DCC/32,  DD/32),  tb>>>(W_DKV, wdkdqh,                     wdkdql,                     DD,  DCC);
    transpose_conv<<<dim3(DCC/32,  DD/32),  tb>>>(W_DQ,  wdkdqh + (size_t)1024*2048, wdkdql + (size_t)1024*2048, DD,  DCC);
    transpose_conv<<<dim3(DHRR/32, DD/32),  tb>>>(W_KR,  wdkdqh + (size_t)2048*2048, wdkdql + (size_t)2048*2048, DD,  DHRR);
    transpose_conv<<<dim3(DD/32,   DCC/32), tb>>>(W_UK,  wukvh,                      wukvl,                      DCC, DD);
    transpose_conv<<<dim3(DD/32,   DCC/32), tb>>>(W_UV,  wukvh + (size_t)2048*1024,  wukvl + (size_t)2048*1024,  DCC, DD);
    transpose_conv<<<dim3(DD/32,   DCC/32), tb>>>(W_UQ,  wuqqrh,                     wuqqrl,                     DCC, DD);
    transpose_conv<<<dim3(DCC/32,  DCC/32), tb>>>(W_QR,  wuqqrh + (size_t)2048*1024, wuqqrl + (size_t)2048*1024, DCC, DCC);
    transpose_conv<<<dim3(DD/32,   DD/32),  tb>>>(W_O,   woh,                        wol,                        DD,  DD);

    constexpr int SMEM128 = 3 * (2*128*128 + 2*128*128);  // 196608
    constexpr int SMEM256 = 2 * (2*128*128 + 2*256*128);  // 196608
    cudaFuncSetAttribute((const void*)gemm_bf16x3<128,3,true>,  cudaFuncAttributeMaxDynamicSharedMemorySize, SMEM128);
    cudaFuncSetAttribute((const void*)gemm_bf16x3<256,2,false>, cudaFuncAttributeMaxDynamicSharedMemorySize, SMEM256);

    // x -> hi/lo
    conv_hilo<<<(MTOK*DD/4 + 255) / 256, 256>>>(x, xh, xl, MTOK*DD/4);

    // fused down projections: [ckv | cq | kr | pad] = x @ [W_DKV | W_DQ | W_KR | 0]
    gemm_bf16x3<128,3,true><<<dim3(CCW/128, MTOK/128), 256, SMEM128>>>(
        xh, xl, DD, wdkdqh, wdkdql, nullptr, cch, ccl, CCW, DD);

    // fused up projections: [kc | vt] = ckv @ [W_UK | W_UV]   (wide 256 tile)
    gemm_bf16x3<256,2,false><<<dim3(4096/256, MTOK/128), 256, SMEM256>>>(
        cch, ccl, CCW, wukvh, wukvl, p_kcvt, nullptr, nullptr, 4096, DCC);
    // [qc | qr] = cq @ [W_UQ | W_QR]
    gemm_bf16x3<256,2,false><<<dim3(3072/256, MTOK/128), 256, SMEM256>>>(
        cch + 1024, ccl + 1024, CCW, wuqqrh, wuqqrl, p_qcqr, nullptr, nullptr, 3072, DCC);

    // pack q/k (hi/lo bf16) + V^T (hi/lo bf16)
    pack_kernel<<<(BB*LL*NHH)/8, 256>>>(s_qk);
    v_transpose_kernel<<<dim3(DHH/32, LL/32, BHT), tb>>>();

    // tensor-core flash attention (heavy q-tiles first)
    cudaFuncSetAttribute(attn_mma_kernel, cudaFuncAttributeMaxDynamicSharedMemorySize, AT_SMEM);
    attn_mma_kernel<<<dim3(BHT, LL/128), 256, AT_SMEM>>>();

    // output projection (wide 256 tile)
    gemm_bf16x3<256,2,false><<<dim3(DD/256, MTOK/128), 256, SMEM256>>>(
        ah, al, DD, woh, wol, out, nullptr, nullptr, DD, DD);
}

// round 10
// speedup vs baseline: 1.0561x; 1.0072x over previous
#include <cuda_runtime.h>
#include <cuda_bf16.h>
#include <math.h>
#include <stdint.h>

// Problem constants
#define BB    4
#define LL    2048
#define DD    2048
#define NHH   16
#define DHH   128
#define DHRR  64
#define DCC   1024
#define MTOK  (BB*LL)          // 8192
#define BHT   (BB*NHH)         // 64
#define CCW   2176             // ckv(1024) | cq(1024) | kr(64) | pad(64)

typedef __nv_bfloat16 bf16;

// ---------------- device scratch (static, no allocation) ----------------
__device__ float g_kcvt [MTOK*4096];        // kc | vt   (cols 0-2047 | 2048-4095)
__device__ float g_qcqr [MTOK*3072];        // qc | qr   (cols 0-2047 | 2048-3071)
__device__ float g_cos  [LL*32];
__device__ float g_sin  [LL*32];

// packed q/k (bh, l, 192) hi/lo bf16; V^T (bh, dh128, l) hi/lo bf16
__device__ bf16 g_qh [BHT*LL*192];
__device__ bf16 g_ql [BHT*LL*192];
__device__ bf16 g_kh [BHT*LL*192];
__device__ bf16 g_kl [BHT*LL*192];
__device__ bf16 g_vth[BHT*DHH*LL];
__device__ bf16 g_vtl[BHT*DHH*LL];

// A-side activations, hi/lo bf16
__device__ bf16 g_x_hi   [MTOK*DD];
__device__ bf16 g_x_lo   [MTOK*DD];
__device__ bf16 g_cc_hi  [MTOK*CCW];        // ckv | cq | kr | pad
__device__ bf16 g_cc_lo  [MTOK*CCW];
__device__ bf16 g_attn_hi[MTOK*DD];
__device__ bf16 g_attn_lo[MTOK*DD];

// B-side weights, transposed to K-major [N,K], hi/lo bf16, N-concatenated
__device__ bf16 g_wdkdq_hi[CCW*2048],  g_wdkdq_lo[CCW*2048];   // DKV^T | DQ^T | KR^T | pad
__device__ bf16 g_wukv_hi [4096*1024], g_wukv_lo [4096*1024];  // UK^T | UV^T
__device__ bf16 g_wuqqr_hi[3072*1024], g_wuqqr_lo[3072*1024];  // UQ^T | QR^T
__device__ bf16 g_wo_hi   [DD*DD],     g_wo_lo   [DD*DD];

// ---------------- helpers ----------------
__device__ __forceinline__ uint32_t smem_u32(const void* p) {
    uint32_t a;
    asm("{ .reg .u64 t; cvta.to.shared.u64 t, %1; cvt.u32.u64 %0, t; }" : "=r"(a) : "l"(p));
    return a;
}

#define CP_ASYNC16(dst, src) \
    asm volatile("cp.async.cg.shared.global [%0], [%1], 16;" :: "r"(dst), "l"(src))
#define CP_COMMIT() asm volatile("cp.async.commit_group;" ::: "memory")
#define CP_WAIT(n)  asm volatile("cp.async.wait_group %0;" :: "n"(n) : "memory")

#define LDSM4(r0, r1, r2, r3, addr) \
    asm volatile("ldmatrix.sync.aligned.m8n8.x4.shared.b16 {%0,%1,%2,%3}, [%4];" \
                 : "=r"(r0), "=r"(r1), "=r"(r2), "=r"(r3) : "r"(addr))

#define MMA_BF16(c, a, b) \
    asm volatile("mma.sync.aligned.m16n8k16.row.col.f32.bf16.bf16.f32 " \
                 "{%0,%1,%2,%3}, {%4,%5,%6,%7}, {%8,%9}, {%0,%1,%2,%3};" \
                 : "+f"((c)[0]), "+f"((c)[1]), "+f"((c)[2]), "+f"((c)[3]) \
                 : "r"((a)[0]), "r"((a)[1]), "r"((a)[2]), "r"((a)[3]), \
                   "r"((b)[0]), "r"((b)[1]))

__device__ __forceinline__ void split_bf16(float x, bf16& hi, bf16& lo) {
    hi = __float2bfloat16_rn(x);
    lo = __float2bfloat16_rn(x - __bfloat162float(hi));
}
__device__ __forceinline__ uint16_t bfb(bf16 v) { return *(uint16_t*)&v; }

__device__ __forceinline__ void split_pack2(float x, float y, uint32_t& hi, uint32_t& lo) {
    bf16 hx, lx, hy, ly;
    split_bf16(x, hx, lx);
    split_bf16(y, hy, ly);
    hi = ((uint32_t)bfb(hy) << 16) | bfb(hx);
    lo = ((uint32_t)bfb(ly) << 16) | bfb(lx);
}

__device__ __forceinline__ uint32_t swz(int row, int c, int rowbytes) {
    int c2 = (c & ~7) | ((c ^ row) & 7);
    return (uint32_t)(row * rowbytes + c2 * 16);
}

// ---------------- rope tables ----------------
__global__ void rope_table_kernel() {
    int i = blockIdx.x * blockDim.x + threadIdx.x;
    if (i >= LL*32) return;
    int l = i >> 5;
    int j = i & 31;
    double invf = pow(10000.0, -(double)j / 32.0);
    double ang  = (double)l * invf;
    g_cos[i] = (float)cos(ang);
    g_sin[i] = (float)sin(ang);
}

// ---------------- convert fp32 -> hi/lo bf16 ----------------
__global__ void __launch_bounds__(256) conv_hilo(const float* __restrict__ in,
                                                 bf16* __restrict__ hi,
                                                 bf16* __restrict__ lo, int n4) {
    int i = blockIdx.x * blockDim.x + threadIdx.x;
    if (i >= n4) return;
    float4 v = *(const float4*)&in[(size_t)i * 4];
    bf16 h[4], l[4];
    split_bf16(v.x, h[0], l[0]);
    split_bf16(v.y, h[1], l[1]);
    split_bf16(v.z, h[2], l[2]);
    split_bf16(v.w, h[3], l[3]);
    *(uint64_t*)&hi[(size_t)i * 4] = *(uint64_t*)h;
    *(uint64_t*)&lo[(size_t)i * 4] = *(uint64_t*)l;
}

// ---------------- transpose + convert: out[C][R] (hi/lo bf16) = in[R][C] ----------------
__global__ void __launch_bounds__(256) transpose_conv(const float* __restrict__ in,
                                                      bf16* __restrict__ out_hi,
                                                      bf16* __restrict__ out_lo,
                                                      int R, int C) {
    __shared__ float t[32][33];
    int bx = blockIdx.x * 32, by = blockIdx.y * 32;
    int tx = threadIdx.x, ty = threadIdx.y;     // (32, 8)
    int x = bx + tx;
#pragma unroll
    for (int j = 0; j < 32; j += 8)
        t[ty + j][tx] = in[(size_t)(by + ty + j) * C + x];
    __syncthreads();
    int xo = by + tx;
#pragma unroll
    for (int j = 0; j < 32; j += 8) {
        float v = t[tx][ty + j];
        bf16 h, l;
        split_bf16(v, h, l);
        size_t o = (size_t)(bx + ty + j) * R + xo;
        out_hi[o] = h;
        out_lo[o] = l;
    }
}

// ---------------- per-head V transpose: g_kcvt cols 2048+ -> (bh, dh, l) hi/lo ----------------
__global__ void __launch_bounds__(256) v_transpose_kernel() {
    __shared__ float t[32][33];
    int dh0 = blockIdx.x * 32;
    int l0  = blockIdx.y * 32;
    int bh  = blockIdx.z;
    int b = bh >> 4, h = bh & 15;
    int tx = threadIdx.x, ty = threadIdx.y;   // (32, 8)
#pragma unroll
    for (int j = 0; j < 32; j += 8)
        t[ty + j][tx] = g_kcvt[(size_t)(b * LL + l0 + ty + j) * 4096 + 2048 + h * DHH + dh0 + tx];
    __syncthreads();
#pragma unroll
    for (int j = 0; j < 32; j += 8) {
        float v = t[tx][ty + j];
        bf16 hh, ll;
        split_bf16(v, hh, ll);
        size_t o = (size_t)bh * DHH * LL + (size_t)(dh0 + ty + j) * LL + l0 + tx;
        g_vth[o] = hh;
        g_vtl[o] = ll;
    }
}

// ---------------- bf16x3 mma.sync GEMM: C[M,N] = A[M,K] @ BT[N,K]^T ----------------
// CTA tile 128 x BN, 3-stage cp.async pipeline, single sync per iteration
// (wait -> sync -> prefetch i+2 -> compute i).
template<int BN, bool HILO>
__global__ void __launch_bounds__(256) gemm_bf16x3(const bf16* __restrict__ Ahi,
                                                   const bf16* __restrict__ Alo,
                                                   int lda,
                                                   const bf16* __restrict__ Bhi,
                                                   const bf16* __restrict__ Blo,
                                                   float* __restrict__ C,
                                                   bf16* __restrict__ Chi,
                                                   bf16* __restrict__ Clo,
                                                   int N, int K) {
    constexpr int ABYTES = 128 * 128;
    constexpr int BBYTES = BN * 128;
    constexpr int STAGE  = 2 * ABYTES + 2 * BBYTES;
    constexpr int WN = BN / 4;
    constexpr int NT = WN / 8;

    extern __shared__ __align__(128) char sm[];
    const uint32_t sbase = smem_u32(sm);

    const int tid  = threadIdx.x;
    const int lane = tid & 31;
    const int warp = tid >> 5;
    const int wm   = (warp >> 2) * 64;
    const int wn   = (warp & 3) * WN;
    const int m0   = blockIdx.y * 128;
    const int n0   = blockIdx.x * BN;
    const int NC   = K >> 6;

    auto load_stage = [&](int chunk, int s) {
        uint32_t sa = sbase + s * STAGE;
        const size_t koff = (size_t)chunk * 64;
#pragma unroll
        for (int it = 0; it < 4; it++) {
            int idx = it * 256 + tid;
            int row = idx >> 3, cw = idx & 7;
            uint32_t off = (uint32_t)(row * 128 + cw * 16);
            off ^= (off >> 3) & 0x70;
            const size_t gofs = (size_t)(m0 + row) * lda + koff + cw * 8;
            CP_ASYNC16(sa + off,          Ahi + gofs);
            CP_ASYNC16(sa + ABYTES + off, Alo + gofs);
        }
        uint32_t sb = sa + 2 * ABYTES;
#pragma unroll
        for (int it = 0; it < BN / 32; it++) {
            int idx = it * 256 + tid;
            int row = idx >> 3, cw = idx & 7;
            uint32_t off = (uint32_t)(row * 128 + cw * 16);
            off ^= (off >> 3) & 0x70;
            const size_t gofs = (size_t)(n0 + row) * K + koff + cw * 8;
            CP_ASYNC16(sb + off,          Bhi + gofs);
            CP_ASYNC16(sb + BBYTES + off, Blo + gofs);
        }
    };

    float acc[4][NT][4];
#pragma unroll
    for (int mt = 0; mt < 4; mt++)
#pragma unroll
        for (int nt = 0; nt < NT; nt++)
#pragma unroll
            for (int i = 0; i < 4; i++) acc[mt][nt][i] = 0.f;

    load_stage(0, 0); CP_COMMIT();
    if (NC > 1) { load_stage(1, 1); CP_COMMIT(); }

    for (int i = 0; i < NC; i++) {
        // chunk i was committed >= 1 full iteration ago; allow the newer one to stay in flight
        if (i + 1 < NC) CP_WAIT(1);
        else            CP_WAIT(0);
        __syncthreads();   // also orders: everyone done READING stage (i+2)%3 (read at iter i-1)

        if (i + 2 < NC) { load_stage(i + 2, (i + 2) % 3); CP_COMMIT(); }

        uint32_t sa = sbase + (i % 3) * STAGE;
        uint32_t sb = sa + 2 * ABYTES;
#pragma unroll
        for (int kk = 0; kk < 4; kk++) {
            const int cb = kk * 32 + ((lane & 16) ? 16 : 0);
            uint32_t ahi[4][4], alo[4][4];
#pragma unroll
            for (int mt = 0; mt < 4; mt++) {
                int row = wm + mt * 16 + (lane & 15);
                uint32_t off = (uint32_t)(row * 128 + cb);
                off ^= (off >> 3) & 0x70;
                LDSM4(ahi[mt][0], ahi[mt][1], ahi[mt][2], ahi[mt][3], sa + off);
                LDSM4(alo[mt][0], alo[mt][1], alo[mt][2], alo[mt][3], sa + ABYTES + off);
            }
            uint32_t bhi[NT][2], blo[NT][2];
#pragma unroll
            for (int nh = 0; nh < NT / 2; nh++) {
                int row = wn + nh * 16 + (lane & 15);
                uint32_t off = (uint32_t)(row * 128 + cb);
                off ^= (off >> 3) & 0x70;
                LDSM4(bhi[nh*2][0], bhi[nh*2+1][0], bhi[nh*2][1], bhi[nh*2+1][1], sb + off);
                LDSM4(blo[nh*2][0], blo[nh*2+1][0], blo[nh*2][1], blo[nh*2+1][1], sb + BBYTES + off);
            }
#pragma unroll
            for (int mt = 0; mt < 4; mt++)
#pragma unroll
                for (int nt = 0; nt < NT; nt++) {
                    MMA_BF16(acc[mt][nt], ahi[mt], bhi[nt]);
                    MMA_BF16(acc[mt][nt], ahi[mt], blo[nt]);
                    MMA_BF16(acc[mt][nt], alo[mt], bhi[nt]);
                }
        }
    }

#pragma unroll
    for (int mt = 0; mt < 4; mt++) {
        int r0 = m0 + wm + mt * 16 + (lane >> 2);
#pragma unroll
        for (int nt = 0; nt < NT; nt++) {
            int c = n0 + wn + nt * 8 + (lane & 3) * 2;
            if (HILO) {
                uint32_t h0, l0, h1, l1;
                split_pack2(acc[mt][nt][0], acc[mt][nt][1], h0, l0);
                split_pack2(acc[mt][nt][2], acc[mt][nt][3], h1, l1);
                *(uint32_t*)&Chi[(size_t)r0 * N + c]       = h0;
                *(uint32_t*)&Clo[(size_t)r0 * N + c]       = l0;
                *(uint32_t*)&Chi[(size_t)(r0 + 8) * N + c] = h1;
                *(uint32_t*)&Clo[(size_t)(r0 + 8) * N + c] = l1;
            } else {
                *(float2*)&C[(size_t)r0 * N + c]       = make_float2(acc[mt][nt][0], acc[mt][nt][1]);
                *(float2*)&C[(size_t)(r0 + 8) * N + c] = make_float2(acc[mt][nt][2], acc[mt][nt][3]);
            }
        }
    }
}

// ---------------- pack: rope + concat + L2-normalize -> hi/lo bf16 ----------------
__global__ void __launch_bounds__(256) pack_kernel(const float* __restrict__ s_qk_ptr) {
    const int tid  = threadIdx.x;
    const int lane = tid & 31;
    const int wid  = tid >> 5;
    int flat = blockIdx.x * 8 + wid;
    const int h = flat % NHH;
    flat /= NHH;
    const int l = flat % LL;
    const int b = flat / LL;

    const int token = b * LL + l;
    const int bh    = b * NHH + h;
    const float sq  = *s_qk_ptr;

    const float cs = g_cos[l * 32 + lane];
    const float sn = g_sin[l * 32 + lane];

    float qv[4];
#pragma unroll
    for (int i = 0; i < 4; i++)
        qv[i] = g_qcqr[(size_t)token * 3072 + h * DHH + i * 32 + lane];
    float qa = g_qcqr[(size_t)token * 3072 + 2048 + h * DHRR + lane];
    float qb = g_qcqr[(size_t)token * 3072 + 2048 + h * DHRR + 32 + lane];
    float qe0 = qa * cs - qb * sn;
    float qe1 = qb * cs + qa * sn;

    float ss = qe0 * qe0 + qe1 * qe1;
#pragma unroll
    for (int i = 0; i < 4; i++) ss += qv[i] * qv[i];
#pragma unroll
    for (int off = 16; off; off >>= 1) ss += __shfl_xor_sync(0xffffffffu, ss, off);
    float qscale = sq / fmaxf(sqrtf(ss), 1e-12f);

    size_t obase = ((size_t)bh * LL + l) * 192;
    bf16 hh, ll;
#pragma unroll
    for (int i = 0; i < 4; i++) {
        split_bf16(qv[i] * qscale, hh, ll);
        g_qh[obase + i * 32 + lane] = hh;
        g_ql[obase + i * 32 + lane] = ll;
    }
    split_bf16(qe0 * qscale, hh, ll);
    g_qh[obase + 128 + lane] = hh; g_ql[obase + 128 + lane] = ll;
    split_bf16(qe1 * qscale, hh, ll);
    g_qh[obase + 160 + lane] = hh; g_ql[obase + 160 + lane] = ll;

    float kv[4];
#pragma unroll
    for (int i = 0; i < 4; i++)
        kv[i] = g_kcvt[(size_t)token * 4096 + h * DHH + i * 32 + lane];
    // k_rope latent from fused down-proj (hi+lo reconstruction)
    float ka = __bfloat162float(g_cc_hi[(size_t)token * CCW + 2048 + lane]) +
               __bfloat162float(g_cc_lo[(size_t)token * CCW + 2048 + lane]);
    float kb = __bfloat162float(g_cc_hi[(size_t)token * CCW + 2048 + 32 + lane]) +
               __bfloat162float(g_cc_lo[(size_t)token * CCW + 2048 + 32 + lane]);
    float ke0 = ka * cs - kb * sn;
    float ke1 = kb * cs + ka * sn;

    float ks = ke0 * ke0 + ke1 * ke1;
#pragma unroll
    for (int i = 0; i < 4; i++) ks += kv[i] * kv[i];
#pragma unroll
    for (int off = 16; off; off >>= 1) ks += __shfl_xor_sync(0xffffffffu, ks, off);
    float kscale = 1.0f / fmaxf(sqrtf(ks), 1e-12f);

#pragma unroll
    for (int i = 0; i < 4; i++) {
        split_bf16(kv[i] * kscale, hh, ll);
        g_kh[obase + i * 32 + lane] = hh;
        g_kl[obase + i * 32 + lane] = ll;
    }
    split_bf16(ke0 * kscale, hh, ll);
    g_kh[obase + 128 + lane] = hh; g_kl[obase + 128 + lane] = ll;
    split_bf16(ke1 * kscale, hh, ll);
    g_kh[obase + 160 + lane] = hh; g_kl[obase + 160 + lane] = ll;
}

// ---------------- tensor-core flash attention (bf16x3), causal ----------------
// Single sync per k-tile: wait -> sync -> prefetch nt+1 -> compute nt.
#define AT_KHI   0
#define AT_KLO   24576
#define AT_VHI   49152
#define AT_VLO   65536
#define AT_STAGE 81920
#define AT_SMEM  (2*AT_STAGE)

__global__ void __launch_bounds__(256, 1) attn_mma_kernel() {
    extern __shared__ __align__(128) char sm[];
    const uint32_t sbase = smem_u32(sm);

    const int tid  = threadIdx.x;
    const int lane = tid & 31;
    const int wid  = tid >> 5;
    // heavy-first: highest q-tiles (most K iterations) launch in the first wave
    const int qt   = (int)(gridDim.y - 1 - blockIdx.y);
    const int bh   = blockIdx.x;
    const int b    = bh >> 4;
    const int h    = bh & 15;

    const size_t qkbase = (size_t)bh * LL * 192;
    const size_t vbase  = (size_t)bh * DHH * LL;

    for (int i = tid; i < 128 * 24; i += 256) {
        int row = i / 24, c = i % 24;
        const size_t gofs = qkbase + (size_t)(qt * 128 + row) * 192 + c * 8;
        CP_ASYNC16(sbase + swz(row, c, 384),            g_qh + gofs);
        CP_ASYNC16(sbase + AT_STAGE + swz(row, c, 384), g_ql + gofs);
    }
    CP_COMMIT(); CP_WAIT(0);
    __syncthreads();

    uint32_t qh[12][4], ql[12][4];
#pragma unroll
    for (int ksi = 0; ksi < 12; ksi++) {
        uint32_t off = swz(wid * 16 + (lane & 15), ksi * 2 + (lane >> 4), 384);
        LDSM4(qh[ksi][0], qh[ksi][1], qh[ksi][2], qh[ksi][3], sbase + off);
        LDSM4(ql[ksi][0], ql[ksi][1], ql[ksi][2], ql[ksi][3], sbase + AT_STAGE + off);
    }
    __syncthreads();

    float o[16][4];
#pragma unroll
    for (int t = 0; t < 16; t++)
#pragma unroll
        for (int j = 0; j < 4; j++) o[t][j] = 0.f;
    float mA = -1e30f, mB = -1e30f, lA = 0.f, lB = 0.f;

    const int NTT = 2 * (qt + 1);

    auto load_tile = [&](int nt, int s) {
        uint32_t st = sbase + s * AT_STAGE;
        const int k0 = nt * 64;
        for (int i = tid; i < 64 * 24; i += 256) {
            int row = i / 24, c = i % 24;
            const size_t gofs = qkbase + (size_t)(k0 + row) * 192 + c * 8;
            CP_ASYNC16(st + AT_KHI + swz(row, c, 384), g_kh + gofs);
            CP_ASYNC16(st + AT_KLO + swz(row, c, 384), g_kl + gofs);
        }
        for (int i = tid; i < 128 * 8; i += 256) {
            int row = i >> 3, c = i & 7;
            const size_t gofs = vbase + (size_t)row * LL + k0 + c * 8;
            CP_ASYNC16(st + AT_VHI + swz(row, c, 128), g_vth + gofs);
            CP_ASYNC16(st + AT_VLO + swz(row, c, 128), g_vtl + gofs);
        }
    };

    load_tile(0, 0); CP_COMMIT();

    for (int nt = 0; nt < NTT; nt++) {
        CP_WAIT(0);          // tile nt is the only pending group
        __syncthreads();     // also orders: everyone done reading stage (nt+1)&1 (iter nt-1)

        if (nt + 1 < NTT) { load_tile(nt + 1, (nt + 1) & 1); CP_COMMIT(); }

        const uint32_t st = sbase + (nt & 1) * AT_STAGE;

        float s[8][4];
#pragma unroll
        for (int t = 0; t < 8; t++)
#pragma unroll
            for (int j = 0; j < 4; j++) s[t][j] = 0.f;

#pragma unroll
        for (int ksi = 0; ksi < 12; ksi++) {
#pragma unroll
            for (int np = 0; np < 4; np++) {
                uint32_t off = swz(np * 16 + (lane & 15), ksi * 2 + (lane >> 4), 384);
                uint32_t kh0, kh1, kh2, kh3, kl0, kl1, kl2, kl3;
                LDSM4(kh0, kh1, kh2, kh3, st + AT_KHI + off);
                LDSM4(kl0, kl1, kl2, kl3, st + AT_KLO + off);
                uint32_t bhe[2] = {kh0, kh2}, bho[2] = {kh1, kh3};
                uint32_t ble[2] = {kl0, kl2}, blo2[2] = {kl1, kl3};
                MMA_BF16(s[2*np],   qh[ksi], bhe);
                MMA_BF16(s[2*np],   qh[ksi], ble);
                MMA_BF16(s[2*np],   ql[ksi], bhe);
                MMA_BF16(s[2*np+1], qh[ksi], bho);
                MMA_BF16(s[2*np+1], qh[ksi], blo2);
                MMA_BF16(s[2*np+1], ql[ksi], bho);
            }
        }

        const int rowA = qt * 128 + wid * 16 + (lane >> 2);
        if (nt * 64 + 63 > rowA) {
#pragma unroll
            for (int t = 0; t < 8; t++) {
                int col = nt * 64 + t * 8 + (lane & 3) * 2;
                if (col > rowA)         s[t][0] = -1e30f;
                if (col + 1 > rowA)     s[t][1] = -1e30f;
                if (col > rowA + 8)     s[t][2] = -1e30f;
                if (col + 1 > rowA + 8) s[t][3] = -1e30f;
            }
        }

        float mxA = -1e30f, mxB = -1e30f;
#pragma unroll
        for (int t = 0; t < 8; t++) {
            mxA = fmaxf(mxA, fmaxf(s[t][0], s[t][1]));
            mxB = fmaxf(mxB, fmaxf(s[t][2], s[t][3]));
        }
        mxA = fmaxf(mxA, __shfl_xor_sync(0xffffffffu, mxA, 1));
        mxA = fmaxf(mxA, __shfl_xor_sync(0xffffffffu, mxA, 2));
        mxB = fmaxf(mxB, __shfl_xor_sync(0xffffffffu, mxB, 1));
        mxB = fmaxf(mxB, __shfl_xor_sync(0xffffffffu, mxB, 2));

        float mnA = fmaxf(mA, mxA), mnB = fmaxf(mB, mxB);
        float scA = __expf(mA - mnA), scB = __expf(mB - mnB);
        mA = mnA; mB = mnB;

        float rsA = 0.f, rsB = 0.f;
#pragma unroll
        for (int t = 0; t < 8; t++) {
            s[t][0] = __expf(s[t][0] - mnA);
            s[t][1] = __expf(s[t][1] - mnA);
            s[t][2] = __expf(s[t][2] - mnB);
            s[t][3] = __expf(s[t][3] - mnB);
            rsA += s[t][0] + s[t][1];
            rsB += s[t][2] + s[t][3];
        }
        rsA += __shfl_xor_sync(0xffffffffu, rsA, 1);
        rsA += __shfl_xor_sync(0xffffffffu, rsA, 2);
        rsB += __shfl_xor_sync(0xffffffffu, rsB, 1);
        rsB += __shfl_xor_sync(0xffffffffu, rsB, 2);
        lA = lA * scA + rsA;
        lB = lB * scB + rsB;

#pragma unroll
        for (int t = 0; t < 16; t++) {
            o[t][0] *= scA; o[t][1] *= scA;
            o[t][2] *= scB; o[t][3] *= scB;
        }

#pragma unroll
        for (int kv = 0; kv < 4; kv++) {
            uint32_t pa_h[4], pa_l[4];
            split_pack2(s[2*kv][0],   s[2*kv][1],   pa_h[0], pa_l[0]);
            split_pack2(s[2*kv][2],   s[2*kv][3],   pa_h[1], pa_l[1]);
            split_pack2(s[2*kv+1][0], s[2*kv+1][1], pa_h[2], pa_l[2]);
            split_pack2(s[2*kv+1][2], s[2*kv+1][3], pa_h[3], pa_l[3]);
#pragma unroll
            for (int np = 0; np < 8; np++) {
                uint32_t off = swz(np * 16 + (lane & 15), kv * 2 + (lane >> 4), 128);
                uint32_t vh0, vh1, vh2, vh3, vl0, vl1, vl2, vl3;
                LDSM4(vh0, vh1, vh2, vh3, st + AT_VHI + off);
                LDSM4(vl0, vl1, vl2, vl3, st + AT_VLO + off);
                uint32_t bhe[2] = {vh0, vh2}, bho[2] = {vh1, vh3};
                uint32_t ble[2] = {vl0, vl2}, blo2[2] = {vl1, vl3};
                MMA_BF16(o[2*np],   pa_h, bhe);
                MMA_BF16(o[2*np],   pa_h, ble);
                MMA_BF16(o[2*np],   pa_l, bhe);
                MMA_BF16(o[2*np+1], pa_h, bho);
                MMA_BF16(o[2*np+1], pa_h, blo2);
                MMA_BF16(o[2*np+1], pa_l, bho);
            }
        }
    }

    // ---- epilogue: write hi/lo bf16 directly (consumed by W_O GEMM) ----
    const float invA = 1.0f / lA, invB = 1.0f / lB;
    const int rowA = qt * 128 + wid * 16 + (lane >> 2);
#pragma unroll
    for (int t = 0; t < 16; t++) {
        int col = t * 8 + (lane & 3) * 2;
        size_t adrA = (size_t)(b * LL + rowA) * DD + h * DHH + col;
        size_t adrB = (size_t)(b * LL + rowA + 8) * DD + h * DHH + col;
        uint32_t hA, lA2, hB, lB2;
        split_pack2(o[t][0] * invA, o[t][1] * invA, hA, lA2);
        split_pack2(o[t][2] * invB, o[t][3] * invB, hB, lB2);
        *(uint32_t*)&g_attn_hi[adrA] = hA;
        *(uint32_t*)&g_attn_lo[adrA] = lA2;
        *(uint32_t*)&g_attn_hi[adrB] = hB;
        *(uint32_t*)&g_attn_lo[adrB] = lB2;
    }
}

// ---------------- launch ----------------
extern "C" void kernel_launch(void* const* d_in, const int* in_sizes, int n_in,
                              void* d_out, int out_size) {
    const float* x     = (const float*)d_in[0];
    const float* W_DKV = (const float*)d_in[1];
    const float* W_UK  = (const float*)d_in[2];
    const float* W_UV  = (const float*)d_in[3];
    const float* W_DQ  = (const float*)d_in[4];
    const float* W_UQ  = (const float*)d_in[5];
    const float* W_QR  = (const float*)d_in[6];
    const float* W_KR  = (const float*)d_in[7];
    const float* W_O   = (const float*)d_in[8];
    const float* s_qk  = (const float*)d_in[9];
    float* out = (float*)d_out;

    float *p_kcvt, *p_qcqr;
    cudaGetSymbolAddress((void**)&p_kcvt, g_kcvt);
    cudaGetSymbolAddress((void**)&p_qcqr, g_qcqr);

    bf16 *xh, *xl, *cch, *ccl, *ah, *al;
    cudaGetSymbolAddress((void**)&xh,  g_x_hi);
    cudaGetSymbolAddress((void**)&xl,  g_x_lo);
    cudaGetSymbolAddress((void**)&cch, g_cc_hi);
    cudaGetSymbolAddress((void**)&ccl, g_cc_lo);
    cudaGetSymbolAddress((void**)&ah,  g_attn_hi);
    cudaGetSymbolAddress((void**)&al,  g_attn_lo);

    bf16 *wdkdqh, *wdkdql, *wukvh, *wukvl, *wuqqrh, *wuqqrl, *woh, *wol;
    cudaGetSymbolAddress((void**)&wdkdqh, g_wdkdq_hi);
    cudaGetSymbolAddress((void**)&wdkdql, g_wdkdq_lo);
    cudaGetSymbolAddress((void**)&wukvh,  g_wukv_hi);
    cudaGetSymbolAddress((void**)&wukvl,  g_wukv_lo);
    cudaGetSymbolAddress((void**)&wuqqrh, g_wuqqr_hi);
    cudaGetSymbolAddress((void**)&wuqqrl, g_wuqqr_lo);
    cudaGetSymbolAddress((void**)&woh,    g_wo_hi);
    cudaGetSymbolAddress((void**)&wol,    g_wo_lo);

    rope_table_kernel<<<(LL*32 + 255) / 256, 256>>>();

    cudaMemsetAsync(wdkdqh + (size_t)2112 * 2048, 0, (size_t)64 * 2048 * sizeof(bf16));
    cudaMemsetAsync(wdkdql + (size_t)2112 * 2048, 0, (size_t)64 * 2048 * sizeof(bf16));

    dim3 tb(32, 8);
    transpose_conv<<<dim3(DCC/32,  DD/32),  tb>>>(W_DKV, wdkdqh,                     wdkdql,                     DD,  DCC);
    transpose_conv<<<dim3(DCC/32,  DD/32),  tb>>>(W_DQ,  wdkdqh + (size_t)1024*2048, wdkdql + (size_t)1024*2048, DD,  DCC);
    transpose_conv<<<dim3(DHRR/32, DD/32),  tb>>>(W_KR,  wdkdqh + (size_t)2048*2048, wdkdql + (size_t)2048*2048, DD,  DHRR);
    transpose_conv<<<dim3(DD/32,   DCC/32), tb>>>(W_UK,  wukvh,                      wukvl,                      DCC, DD);
    transpose_conv<<<dim3(DD/32,   DCC/32), tb>>>(W_UV,  wukvh + (size_t)2048*1024,  wukvl + (size_t)2048*1024,  DCC, DD);
    transpose_conv<<<dim3(DD/32,   DCC/32), tb>>>(W_UQ,  wuqqrh,                     wuqqrl,                     DCC, DD);
    transpose_conv<<<dim3(DCC/32,  DCC/32), tb>>>(W_QR,  wuqqrh + (size_t)2048*1024, wuqqrl + (size_t)2048*1024, DCC, DCC);
    transpose_conv<<<dim3(DD/32,   DD/32),  tb>>>(W_O,   woh,                        wol,                        DD,  DD);

    constexpr int SMEM128 = 3 * (2*128*128 + 2*128*128);  // 196608
    cudaFuncSetAttribute((const void*)gemm_bf16x3<128,true>,  cudaFuncAttributeMaxDynamicSharedMemorySize, SMEM128);
    cudaFuncSetAttribute((const void*)gemm_bf16x3<128,false>, cudaFuncAttributeMaxDynamicSharedMemorySize, SMEM128);

    // x -> hi/lo
    conv_hilo<<<(MTOK*DD/4 + 255) / 256, 256>>>(x, xh, xl, MTOK*DD/4);

    // fused down projections: [ckv | cq | kr | pad] = x @ [W_DKV | W_DQ | W_KR | 0]
    gemm_bf16x3<128,true><<<dim3(CCW/128, MTOK/128), 256, SMEM128>>>(
        xh, xl, DD, wdkdqh, wdkdql, nullptr, cch, ccl, CCW, DD);

    // fused up projections: [kc | vt] = ckv @ [W_UK | W_UV]
    gemm_bf16x3<128,false><<<dim3(4096/128, MTOK/128), 256, SMEM128>>>(
        cch, ccl, CCW, wukvh, wukvl, p_kcvt, nullptr, nullptr, 4096, DCC);
    // [qc | qr] = cq @ [W_UQ | W_QR]
    gemm_bf16x3<128,false><<<dim3(3072/128, MTOK/128), 256, SMEM128>>>(
        cch + 1024, ccl + 1024, CCW, wuqqrh, wuqqrl, p_qcqr, nullptr, nullptr, 3072, DCC);

    // pack q/k (hi/lo bf16) + V^T (hi/lo bf16)
    pack_kernel<<<(BB*LL*NHH)/8, 256>>>(s_qk);
    v_transpose_kernel<<<dim3(DHH/32, LL/32, BHT), tb>>>();

    // tensor-core flash attention (heavy q-tiles first)
    cudaFuncSetAttribute(attn_mma_kernel, cudaFuncAttributeMaxDynamicSharedMemorySize, AT_SMEM);
    attn_mma_kernel<<<dim3(BHT, LL/128), 256, AT_SMEM>>>();

    // output projection
    gemm_bf16x3<128,false><<<dim3(DD/128, MTOK/128), 256, SMEM128>>>(
        ah, al, DD, woh, wol, out, nullptr, nullptr, DD, DD);
}

// round 12
// speedup vs baseline: 1.0702x; 1.0133x over previous
#include <cuda_runtime.h>
#include <cuda_bf16.h>
#include <math.h>
#include <stdint.h>

// Problem constants
#define BB    4
#define LL    2048
#define DD    2048
#define NHH   16
#define DHH   128
#define DHRR  64
#define DCC   1024
#define MTOK  (BB*LL)          // 8192
#define BHT   (BB*NHH)         // 64
#define CCW   2176             // ckv(1024) | cq(1024) | kr(64) | pad(64)

typedef __nv_bfloat16 bf16;

// ---------------- device scratch (static, no allocation) ----------------
__device__ float g_kcvt [MTOK*4096];        // kc | vt   (cols 0-2047 | 2048-4095)
__device__ float g_qcqr [MTOK*3072];        // qc | qr   (cols 0-2047 | 2048-3071)
__device__ float g_cos  [LL*32];
__device__ float g_sin  [LL*32];

// packed q/k (bh, l, 192) hi/lo bf16; V^T (bh, dh128, l) hi/lo bf16
__device__ bf16 g_qh [BHT*LL*192];
__device__ bf16 g_ql [BHT*LL*192];
__device__ bf16 g_kh [BHT*LL*192];
__device__ bf16 g_kl [BHT*LL*192];
__device__ bf16 g_vth[BHT*DHH*LL];
__device__ bf16 g_vtl[BHT*DHH*LL];

// A-side activations, hi/lo bf16
__device__ bf16 g_x_hi   [MTOK*DD];
__device__ bf16 g_x_lo   [MTOK*DD];
__device__ bf16 g_cc_hi  [MTOK*CCW];        // ckv | cq | kr | pad
__device__ bf16 g_cc_lo  [MTOK*CCW];
__device__ bf16 g_attn_hi[MTOK*DD];
__device__ bf16 g_attn_lo[MTOK*DD];

// B-side weights, transposed to K-major [N,K], hi/lo bf16, N-concatenated
__device__ bf16 g_wdkdq_hi[CCW*2048],  g_wdkdq_lo[CCW*2048];   // DKV^T | DQ^T | KR^T | pad
__device__ bf16 g_wukv_hi [4096*1024], g_wukv_lo [4096*1024];  // UK^T | UV^T
__device__ bf16 g_wuqqr_hi[3072*1024], g_wuqqr_lo[3072*1024];  // UQ^T | QR^T
__device__ bf16 g_wo_hi   [DD*DD],     g_wo_lo   [DD*DD];

// ---------------- helpers ----------------
__device__ __forceinline__ uint32_t smem_u32(const void* p) {
    uint32_t a;
    asm("{ .reg .u64 t; cvta.to.shared.u64 t, %1; cvt.u32.u64 %0, t; }" : "=r"(a) : "l"(p));
    return a;
}

#define CP_ASYNC16(dst, src) \
    asm volatile("cp.async.cg.shared.global [%0], [%1], 16;" :: "r"(dst), "l"(src))
#define CP_COMMIT() asm volatile("cp.async.commit_group;" ::: "memory")
#define CP_WAIT(n)  asm volatile("cp.async.wait_group %0;" :: "n"(n) : "memory")

#define LDSM4(r0, r1, r2, r3, addr) \
    asm volatile("ldmatrix.sync.aligned.m8n8.x4.shared.b16 {%0,%1,%2,%3}, [%4];" \
                 : "=r"(r0), "=r"(r1), "=r"(r2), "=r"(r3) : "r"(addr))

#define MMA_BF16(c, a, b) \
    asm volatile("mma.sync.aligned.m16n8k16.row.col.f32.bf16.bf16.f32 " \
                 "{%0,%1,%2,%3}, {%4,%5,%6,%7}, {%8,%9}, {%0,%1,%2,%3};" \
                 : "+f"((c)[0]), "+f"((c)[1]), "+f"((c)[2]), "+f"((c)[3]) \
                 : "r"((a)[0]), "r"((a)[1]), "r"((a)[2]), "r"((a)[3]), \
                   "r"((b)[0]), "r"((b)[1]))

__device__ __forceinline__ void split_bf16(float x, bf16& hi, bf16& lo) {
    hi = __float2bfloat16_rn(x);
    lo = __float2bfloat16_rn(x - __bfloat162float(hi));
}
__device__ __forceinline__ uint16_t bfb(bf16 v) { return *(uint16_t*)&v; }

// round-nearest split+pack (used in memory-bound conversion kernels)
__device__ __forceinline__ void split_pack2(float x, float y, uint32_t& hi, uint32_t& lo) {
    bf16 hx, lx, hy, ly;
    split_bf16(x, hx, lx);
    split_bf16(y, hy, ly);
    hi = ((uint32_t)bfb(hy) << 16) | bfb(hx);
    lo = ((uint32_t)bfb(ly) << 16) | bfb(lx);
}

// fast exact-truncation split+pack: hi = top-16-bits of x,y via one PRMT (exact),
// lo = residual rounded once via cvt.rn.bf16x2. hi+lo identical accuracy class.
__device__ __forceinline__ void split_pack2_fast(float x, float y, uint32_t& hi, uint32_t& lo) {
    uint32_t bx = __float_as_uint(x), by = __float_as_uint(y);
    uint32_t h;
    asm("prmt.b32 %0, %1, %2, 0x7632;" : "=r"(h) : "r"(bx), "r"(by));
    float lx = x - __uint_as_float(bx & 0xFFFF0000u);
    float ly = y - __uint_as_float(by & 0xFFFF0000u);
    uint32_t l;
    asm("cvt.rn.satfinite.bf16x2.f32 %0, %1, %2;" : "=r"(l) : "f"(ly), "f"(lx));
    hi = h; lo = l;
}

__device__ __forceinline__ uint32_t swz(int row, int c, int rowbytes) {
    int c2 = (c & ~7) | ((c ^ row) & 7);
    return (uint32_t)(row * rowbytes + c2 * 16);
}

// ---------------- rope tables ----------------
__global__ void rope_table_kernel() {
    int i = blockIdx.x * blockDim.x + threadIdx.x;
    if (i >= LL*32) return;
    int l = i >> 5;
    int j = i & 31;
    double invf = pow(10000.0, -(double)j / 32.0);
    double ang  = (double)l * invf;
    g_cos[i] = (float)cos(ang);
    g_sin[i] = (float)sin(ang);
}

// ---------------- convert fp32 -> hi/lo bf16 ----------------
__global__ void __launch_bounds__(256) conv_hilo(const float* __restrict__ in,
                                                 bf16* __restrict__ hi,
                                                 bf16* __restrict__ lo, int n4) {
    int i = blockIdx.x * blockDim.x + threadIdx.x;
    if (i >= n4) return;
    float4 v = *(const float4*)&in[(size_t)i * 4];
    bf16 h[4], l[4];
    split_bf16(v.x, h[0], l[0]);
    split_bf16(v.y, h[1], l[1]);
    split_bf16(v.z, h[2], l[2]);
    split_bf16(v.w, h[3], l[3]);
    *(uint64_t*)&hi[(size_t)i * 4] = *(uint64_t*)h;
    *(uint64_t*)&lo[(size_t)i * 4] = *(uint64_t*)l;
}

// ---------------- transpose + convert: out[C][R] (hi/lo bf16) = in[R][C] ----------------
__global__ void __launch_bounds__(256) transpose_conv(const float* __restrict__ in,
                                                      bf16* __restrict__ out_hi,
                                                      bf16* __restrict__ out_lo,
                                                      int R, int C) {
    __shared__ float t[32][33];
    int bx = blockIdx.x * 32, by = blockIdx.y * 32;
    int tx = threadIdx.x, ty = threadIdx.y;     // (32, 8)
    int x = bx + tx;
#pragma unroll
    for (int j = 0; j < 32; j += 8)
        t[ty + j][tx] = in[(size_t)(by + ty + j) * C + x];
    __syncthreads();
    int xo = by + tx;
#pragma unroll
    for (int j = 0; j < 32; j += 8) {
        float v = t[tx][ty + j];
        bf16 h, l;
        split_bf16(v, h, l);
        size_t o = (size_t)(bx + ty + j) * R + xo;
        out_hi[o] = h;
        out_lo[o] = l;
    }
}

// ---------------- per-head V transpose: g_kcvt cols 2048+ -> (bh, dh, l) hi/lo ----------------
__global__ void __launch_bounds__(256) v_transpose_kernel() {
    __shared__ float t[32][33];
    int dh0 = blockIdx.x * 32;
    int l0  = blockIdx.y * 32;
    int bh  = blockIdx.z;
    int b = bh >> 4, h = bh & 15;
    int tx = threadIdx.x, ty = threadIdx.y;   // (32, 8)
#pragma unroll
    for (int j = 0; j < 32; j += 8)
        t[ty + j][tx] = g_kcvt[(size_t)(b * LL + l0 + ty + j) * 4096 + 2048 + h * DHH + dh0 + tx];
    __syncthreads();
#pragma unroll
    for (int j = 0; j < 32; j += 8) {
        float v = t[tx][ty + j];
        bf16 hh, ll;
        split_bf16(v, hh, ll);
        size_t o = (size_t)bh * DHH * LL + (size_t)(dh0 + ty + j) * LL + l0 + tx;
        g_vth[o] = hh;
        g_vtl[o] = ll;
    }
}

// ---------------- bf16x3 mma.sync GEMM: C[M,N] = A[M,K] @ BT[N,K]^T ----------------
// CTA tile 128 x BN, 3-stage cp.async pipeline (R7 structure — best known).
template<int BN, bool HILO>
__global__ void __launch_bounds__(256) gemm_bf16x3(const bf16* __restrict__ Ahi,
                                                   const bf16* __restrict__ Alo,
                                                   int lda,
                                                   const bf16* __restrict__ Bhi,
                                                   const bf16* __restrict__ Blo,
                                                   float* __restrict__ C,
                                                   bf16* __restrict__ Chi,
                                                   bf16* __restrict__ Clo,
                                                   int N, int K) {
    constexpr int ABYTES = 128 * 128;
    constexpr int BBYTES = BN * 128;
    constexpr int STAGE  = 2 * ABYTES + 2 * BBYTES;
    constexpr int WN = BN / 4;
    constexpr int NT = WN / 8;

    extern __shared__ __align__(128) char sm[];
    const uint32_t sbase = smem_u32(sm);

    const int tid  = threadIdx.x;
    const int lane = tid & 31;
    const int warp = tid >> 5;
    const int wm   = (warp >> 2) * 64;
    const int wn   = (warp & 3) * WN;
    const int m0   = blockIdx.y * 128;
    const int n0   = blockIdx.x * BN;
    const int NC   = K >> 6;

    auto load_stage = [&](int chunk, int s) {
        uint32_t sa = sbase + s * STAGE;
        const size_t koff = (size_t)chunk * 64;
#pragma unroll
        for (int it = 0; it < 4; it++) {
            int idx = it * 256 + tid;
            int row = idx >> 3, cw = idx & 7;
            uint32_t off = (uint32_t)(row * 128 + cw * 16);
            off ^= (off >> 3) & 0x70;
            const size_t gofs = (size_t)(m0 + row) * lda + koff + cw * 8;
            CP_ASYNC16(sa + off,          Ahi + gofs);
            CP_ASYNC16(sa + ABYTES + off, Alo + gofs);
        }
        uint32_t sb = sa + 2 * ABYTES;
#pragma unroll
        for (int it = 0; it < BN / 32; it++) {
            int idx = it * 256 + tid;
            int row = idx >> 3, cw = idx & 7;
            uint32_t off = (uint32_t)(row * 128 + cw * 16);
            off ^= (off >> 3) & 0x70;
            const size_t gofs = (size_t)(n0 + row) * K + koff + cw * 8;
            CP_ASYNC16(sb + off,          Bhi + gofs);
            CP_ASYNC16(sb + BBYTES + off, Blo + gofs);
        }
    };

    float acc[4][NT][4];
#pragma unroll
    for (int mt = 0; mt < 4; mt++)
#pragma unroll
        for (int nt = 0; nt < NT; nt++)
#pragma unroll
            for (int i = 0; i < 4; i++) acc[mt][nt][i] = 0.f;

    load_stage(0, 0); CP_COMMIT();
    if (NC > 1) { load_stage(1, 1); CP_COMMIT(); }

    for (int i = 0; i < NC; i++) {
        if (i + 2 < NC) { load_stage(i + 2, (i + 2) % 3); CP_COMMIT(); }
        if (i + 2 < NC)      CP_WAIT(2);
        else if (i + 1 < NC) CP_WAIT(1);
        else                 CP_WAIT(0);
        __syncthreads();

        uint32_t sa = sbase + (i % 3) * STAGE;
        uint32_t sb = sa + 2 * ABYTES;
#pragma unroll
        for (int kk = 0; kk < 4; kk++) {
            const int cb = kk * 32 + ((lane & 16) ? 16 : 0);
            uint32_t ahi[4][4], alo[4][4];
#pragma unroll
            for (int mt = 0; mt < 4; mt++) {
                int row = wm + mt * 16 + (lane & 15);
                uint32_t off = (uint32_t)(row * 128 + cb);
                off ^= (off >> 3) & 0x70;
                LDSM4(ahi[mt][0], ahi[mt][1], ahi[mt][2], ahi[mt][3], sa + off);
                LDSM4(alo[mt][0], alo[mt][1], alo[mt][2], alo[mt][3], sa + ABYTES + off);
            }
            uint32_t bhi[NT][2], blo[NT][2];
#pragma unroll
            for (int nh = 0; nh < NT / 2; nh++) {
                int row = wn + nh * 16 + (lane & 15);
                uint32_t off = (uint32_t)(row * 128 + cb);
                off ^= (off >> 3) & 0x70;
                LDSM4(bhi[nh*2][0], bhi[nh*2+1][0], bhi[nh*2][1], bhi[nh*2+1][1], sb + off);
                LDSM4(blo[nh*2][0], blo[nh*2+1][0], blo[nh*2][1], blo[nh*2+1][1], sb + BBYTES + off);
            }
#pragma unroll
            for (int mt = 0; mt < 4; mt++)
#pragma unroll
                for (int nt = 0; nt < NT; nt++) {
                    MMA_BF16(acc[mt][nt], ahi[mt], bhi[nt]);
                    MMA_BF16(acc[mt][nt], ahi[mt], blo[nt]);
                    MMA_BF16(acc[mt][nt], alo[mt], bhi[nt]);
                }
        }
        __syncthreads();
    }

#pragma unroll
    for (int mt = 0; mt < 4; mt++) {
        int r0 = m0 + wm + mt * 16 + (lane >> 2);
#pragma unroll
        for (int nt = 0; nt < NT; nt++) {
            int c = n0 + wn + nt * 8 + (lane & 3) * 2;
            if (HILO) {
                uint32_t h0, l0, h1, l1;
                split_pack2_fast(acc[mt][nt][0], acc[mt][nt][1], h0, l0);
                split_pack2_fast(acc[mt][nt][2], acc[mt][nt][3], h1, l1);
                *(uint32_t*)&Chi[(size_t)r0 * N + c]       = h0;
                *(uint32_t*)&Clo[(size_t)r0 * N + c]       = l0;
                *(uint32_t*)&Chi[(size_t)(r0 + 8) * N + c] = h1;
                *(uint32_t*)&Clo[(size_t)(r0 + 8) * N + c] = l1;
            } else {
                *(float2*)&C[(size_t)r0 * N + c]       = make_float2(acc[mt][nt][0], acc[mt][nt][1]);
                *(float2*)&C[(size_t)(r0 + 8) * N + c] = make_float2(acc[mt][nt][2], acc[mt][nt][3]);
            }
        }
    }
}

// ---------------- pack: rope + concat + L2-normalize -> hi/lo bf16 ----------------
__global__ void __launch_bounds__(256) pack_kernel(const float* __restrict__ s_qk_ptr) {
    const int tid  = threadIdx.x;
    const int lane = tid & 31;
    const int wid  = tid >> 5;
    int flat = blockIdx.x * 8 + wid;
    const int h = flat % NHH;
    flat /= NHH;
    const int l = flat % LL;
    const int b = flat / LL;

    const int token = b * LL + l;
    const int bh    = b * NHH + h;
    const float sq  = *s_qk_ptr;

    const float cs = g_cos[l * 32 + lane];
    const float sn = g_sin[l * 32 + lane];

    float qv[4];
#pragma unroll
    for (int i = 0; i < 4; i++)
        qv[i] = g_qcqr[(size_t)token * 3072 + h * DHH + i * 32 + lane];
    float qa = g_qcqr[(size_t)token * 3072 + 2048 + h * DHRR + lane];
    float qb = g_qcqr[(size_t)token * 3072 + 2048 + h * DHRR + 32 + lane];
    float qe0 = qa * cs - qb * sn;
    float qe1 = qb * cs + qa * sn;

    float ss = qe0 * qe0 + qe1 * qe1;
#pragma unroll
    for (int i = 0; i < 4; i++) ss += qv[i] * qv[i];
#pragma unroll
    for (int off = 16; off; off >>= 1) ss += __shfl_xor_sync(0xffffffffu, ss, off);
    float qscale = sq / fmaxf(sqrtf(ss), 1e-12f);

    size_t obase = ((size_t)bh * LL + l) * 192;
    bf16 hh, ll;
#pragma unroll
    for (int i = 0; i < 4; i++) {
        split_bf16(qv[i] * qscale, hh, ll);
        g_qh[obase + i * 32 + lane] = hh;
        g_ql[obase + i * 32 + lane] = ll;
    }
    split_bf16(qe0 * qscale, hh, ll);
    g_qh[obase + 128 + lane] = hh; g_ql[obase + 128 + lane] = ll;
    split_bf16(qe1 * qscale, hh, ll);
    g_qh[obase + 160 + lane] = hh; g_ql[obase + 160 + lane] = ll;

    float kv[4];
#pragma unroll
    for (int i = 0; i < 4; i++)
        kv[i] = g_kcvt[(size_t)token * 4096 + h * DHH + i * 32 + lane];
    // k_rope latent from fused down-proj (hi+lo reconstruction)
    float ka = __bfloat162float(g_cc_hi[(size_t)token * CCW + 2048 + lane]) +
               __bfloat162float(g_cc_lo[(size_t)token * CCW + 2048 + lane]);
    float kb = __bfloat162float(g_cc_hi[(size_t)token * CCW + 2048 + 32 + lane]) +
               __bfloat162float(g_cc_lo[(size_t)token * CCW + 2048 + 32 + lane]);
    float ke0 = ka * cs - kb * sn;
    float ke1 = kb * cs + ka * sn;

    float ks = ke0 * ke0 + ke1 * ke1;
#pragma unroll
    for (int i = 0; i < 4; i++) ks += kv[i] * kv[i];
#pragma unroll
    for (int off = 16; off; off >>= 1) ks += __shfl_xor_sync(0xffffffffu, ks, off);
    float kscale = 1.0f / fmaxf(sqrtf(ks), 1e-12f);

#pragma unroll
    for (int i = 0; i < 4; i++) {
        split_bf16(kv[i] * kscale, hh, ll);
        g_kh[obase + i * 32 + lane] = hh;
        g_kl[obase + i * 32 + lane] = ll;
    }
    split_bf16(ke0 * kscale, hh, ll);
    g_kh[obase + 128 + lane] = hh; g_kl[obase + 128 + lane] = ll;
    split_bf16(ke1 * kscale, hh, ll);
    g_kh[obase + 160 + lane] = hh; g_kl[obase + 160 + lane] = ll;
}

// ---------------- tensor-core flash attention (bf16x3), causal ----------------
#define AT_KHI   0
#define AT_KLO   24576
#define AT_VHI   49152
#define AT_VLO   65536
#define AT_STAGE 81920
#define AT_SMEM  (2*AT_STAGE)

__global__ void __launch_bounds__(256, 1) attn_mma_kernel() {
    extern __shared__ __align__(128) char sm[];
    const uint32_t sbase = smem_u32(sm);

    const int tid  = threadIdx.x;
    const int lane = tid & 31;
    const int wid  = tid >> 5;
    // heavy-first: highest q-tiles (most K iterations) launch in the first wave
    const int qt   = (int)(gridDim.y - 1 - blockIdx.y);
    const int bh   = blockIdx.x;
    const int b    = bh >> 4;
    const int h    = bh & 15;

    const size_t qkbase = (size_t)bh * LL * 192;
    const size_t vbase  = (size_t)bh * DHH * LL;

    for (int i = tid; i < 128 * 24; i += 256) {
        int row = i / 24, c = i % 24;
        const size_t gofs = qkbase + (size_t)(qt * 128 + row) * 192 + c * 8;
        CP_ASYNC16(sbase + swz(row, c, 384),            g_qh + gofs);
        CP_ASYNC16(sbase + AT_STAGE + swz(row, c, 384), g_ql + gofs);
    }
    CP_COMMIT(); CP_WAIT(0);
    __syncthreads();

    uint32_t qh[12][4], ql[12][4];
#pragma unroll
    for (int ksi = 0; ksi < 12; ksi++) {
        uint32_t off = swz(wid * 16 + (lane & 15), ksi * 2 + (lane >> 4), 384);
        LDSM4(qh[ksi][0], qh[ksi][1], qh[ksi][2], qh[ksi][3], sbase + off);
        LDSM4(ql[ksi][0], ql[ksi][1], ql[ksi][2], ql[ksi][3], sbase + AT_STAGE + off);
    }
    __syncthreads();

    float o[16][4];
#pragma unroll
    for (int t = 0; t < 16; t++)
#pragma unroll
        for (int j = 0; j < 4; j++) o[t][j] = 0.f;
    float mA = -1e30f, mB = -1e30f, lA = 0.f, lB = 0.f;

    const int NTT = 2 * (qt + 1);

    auto load_tile = [&](int nt, int s) {
        uint32_t st = sbase + s * AT_STAGE;
        const int k0 = nt * 64;
        for (int i = tid; i < 64 * 24; i += 256) {
            int row = i / 24, c = i % 24;
            const size_t gofs = qkbase + (size_t)(k0 + row) * 192 + c * 8;
            CP_ASYNC16(st + AT_KHI + swz(row, c, 384), g_kh + gofs);
            CP_ASYNC16(st + AT_KLO + swz(row, c, 384), g_kl + gofs);
        }
        for (int i = tid; i < 128 * 8; i += 256) {
            int row = i >> 3, c = i & 7;
            const size_t gofs = vbase + (size_t)row * LL + k0 + c * 8;
            CP_ASYNC16(st + AT_VHI + swz(row, c, 128), g_vth + gofs);
            CP_ASYNC16(st + AT_VLO + swz(row, c, 128), g_vtl + gofs);
        }
    };

    load_tile(0, 0); CP_COMMIT();

    for (int nt = 0; nt < NTT; nt++) {
        if (nt + 1 < NTT) { load_tile(nt + 1, (nt + 1) & 1); CP_COMMIT(); CP_WAIT(1); }
        else              { CP_WAIT(0); }
        __syncthreads();

        const uint32_t st = sbase + (nt & 1) * AT_STAGE;

        float s[8][4];
#pragma unroll
        for (int t = 0; t < 8; t++)
#pragma unroll
            for (int j = 0; j < 4; j++) s[t][j] = 0.f;

#pragma unroll
        for (int ksi = 0; ksi < 12; ksi++) {
#pragma unroll
            for (int np = 0; np < 4; np++) {
                uint32_t off = swz(np * 16 + (lane & 15), ksi * 2 + (lane >> 4), 384);
                uint32_t kh0, kh1, kh2, kh3, kl0, kl1, kl2, kl3;
                LDSM4(kh0, kh1, kh2, kh3, st + AT_KHI + off);
                LDSM4(kl0, kl1, kl2, kl3, st + AT_KLO + off);
                uint32_t bhe[2] = {kh0, kh2}, bho[2] = {kh1, kh3};
                uint32_t ble[2] = {kl0, kl2}, blo2[2] = {kl1, kl3};
                MMA_BF16(s[2*np],   qh[ksi], bhe);
                MMA_BF16(s[2*np],   qh[ksi], ble);
                MMA_BF16(s[2*np],   ql[ksi], bhe);
                MMA_BF16(s[2*np+1], qh[ksi], bho);
                MMA_BF16(s[2*np+1], qh[ksi], blo2);
                MMA_BF16(s[2*np+1], ql[ksi], bho);
            }
        }

        const int rowA = qt * 128 + wid * 16 + (lane >> 2);
        if (nt * 64 + 63 > rowA) {
#pragma unroll
            for (int t = 0; t < 8; t++) {
                int col = nt * 64 + t * 8 + (lane & 3) * 2;
                if (col > rowA)         s[t][0] = -1e30f;
                if (col + 1 > rowA)     s[t][1] = -1e30f;
                if (col > rowA + 8)     s[t][2] = -1e30f;
                if (col + 1 > rowA + 8) s[t][3] = -1e30f;
            }
        }

        float mxA = -1e30f, mxB = -1e30f;
#pragma unroll
        for (int t = 0; t < 8; t++) {
            mxA = fmaxf(mxA, fmaxf(s[t][0], s[t][1]));
            mxB = fmaxf(mxB, fmaxf(s[t][2], s[t][3]));
        }
        mxA = fmaxf(mxA, __shfl_xor_sync(0xffffffffu, mxA, 1));
        mxA = fmaxf(mxA, __shfl_xor_sync(0xffffffffu, mxA, 2));
        mxB = fmaxf(mxB, __shfl_xor_sync(0xffffffffu, mxB, 1));
        mxB = fmaxf(mxB, __shfl_xor_sync(0xffffffffu, mxB, 2));

        float mnA = fmaxf(mA, mxA), mnB = fmaxf(mB, mxB);
        float scA = __expf(mA - mnA), scB = __expf(mB - mnB);
        mA = mnA; mB = mnB;

        float rsA = 0.f, rsB = 0.f;
#pragma unroll
        for (int t = 0; t < 8; t++) {
            s[t][0] = __expf(s[t][0] - mnA);
            s[t][1] = __expf(s[t][1] - mnA);
            s[t][2] = __expf(s[t][2] - mnB);
            s[t][3] = __expf(s[t][3] - mnB);
            rsA += s[t][0] + s[t][1];
            rsB += s[t][2] + s[t][3];
        }
        rsA += __shfl_xor_sync(0xffffffffu, rsA, 1);
        rsA += __shfl_xor_sync(0xffffffffu, rsA, 2);
        rsB += __shfl_xor_sync(0xffffffffu, rsB, 1);
        rsB += __shfl_xor_sync(0xffffffffu, rsB, 2);
        lA = lA * scA + rsA;
        lB = lB * scB + rsB;

#pragma unroll
        for (int t = 0; t < 16; t++) {
            o[t][0] *= scA; o[t][1] *= scA;
            o[t][2] *= scB; o[t][3] *= scB;
        }

#pragma unroll
        for (int kv = 0; kv < 4; kv++) {
            uint32_t pa_h[4], pa_l[4];
            split_pack2_fast(s[2*kv][0],   s[2*kv][1],   pa_h[0], pa_l[0]);
            split_pack2_fast(s[2*kv][2],   s[2*kv][3],   pa_h[1], pa_l[1]);
            split_pack2_fast(s[2*kv+1][0], s[2*kv+1][1], pa_h[2], pa_l[2]);
            split_pack2_fast(s[2*kv+1][2], s[2*kv+1][3], pa_h[3], pa_l[3]);
#pragma unroll
            for (int np = 0; np < 8; np++) {
                uint32_t off = swz(np * 16 + (lane & 15), kv * 2 + (lane >> 4), 128);
                uint32_t vh0, vh1, vh2, vh3, vl0, vl1, vl2, vl3;
                LDSM4(vh0, vh1, vh2, vh3, st + AT_VHI + off);
                LDSM4(vl0, vl1, vl2, vl3, st + AT_VLO + off);
                uint32_t bhe[2] = {vh0, vh2}, bho[2] = {vh1, vh3};
                uint32_t ble[2] = {vl0, vl2}, blo2[2] = {vl1, vl3};
                MMA_BF16(o[2*np],   pa_h, bhe);
                MMA_BF16(o[2*np],   pa_h, ble);
                MMA_BF16(o[2*np],   pa_l, bhe);
                MMA_BF16(o[2*np+1], pa_h, bho);
                MMA_BF16(o[2*np+1], pa_h, blo2);
                MMA_BF16(o[2*np+1], pa_l, bho);
            }
        }
        __syncthreads();
    }

    // ---- epilogue: write hi/lo bf16 directly (consumed by W_O GEMM) ----
    const float invA = 1.0f / lA, invB = 1.0f / lB;
    const int rowA = qt * 128 + wid * 16 + (lane >> 2);
#pragma unroll
    for (int t = 0; t < 16; t++) {
        int col = t * 8 + (lane & 3) * 2;
        size_t adrA = (size_t)(b * LL + rowA) * DD + h * DHH + col;
        size_t adrB = (size_t)(b * LL + rowA + 8) * DD + h * DHH + col;
        uint32_t hA, lA2, hB, lB2;
        split_pack2_fast(o[t][0] * invA, o[t][1] * invA, hA, lA2);
        split_pack2_fast(o[t][2] * invB, o[t][3] * invB, hB, lB2);
        *(uint32_t*)&g_attn_hi[adrA] = hA;
        *(uint32_t*)&g_attn_lo[adrA] = lA2;
        *(uint32_t*)&g_attn_hi[adrB] = hB;
        *(uint32_t*)&g_attn_lo[adrB] = lB2;
    }
}

// ---------------- launch ----------------
extern "C" void kernel_launch(void* const* d_in, const int* in_sizes, int n_in,
                              void* d_out, int out_size) {
    const float* x     = (const float*)d_in[0];
    const float* W_DKV = (const float*)d_in[1];
    const float* W_UK  = (const float*)d_in[2];
    const float* W_UV  = (const float*)d_in[3];
    const float* W_DQ  = (const float*)d_in[4];
    const float* W_UQ  = (const float*)d_in[5];
    const float* W_QR  = (const float*)d_in[6];
    const float* W_KR  = (const float*)d_in[7];
    const float* W_O   = (const float*)d_in[8];
    const float* s_qk  = (const float*)d_in[9];
    float* out = (float*)d_out;

    float *p_kcvt, *p_qcqr;
    cudaGetSymbolAddress((void**)&p_kcvt, g_kcvt);
    cudaGetSymbolAddress((void**)&p_qcqr, g_qcqr);

    bf16 *xh, *xl, *cch, *ccl, *ah, *al;
    cudaGetSymbolAddress((void**)&xh,  g_x_hi);
    cudaGetSymbolAddress((void**)&xl,  g_x_lo);
    cudaGetSymbolAddress((void**)&cch, g_cc_hi);
    cudaGetSymbolAddress((void**)&ccl, g_cc_lo);
    cudaGetSymbolAddress((void**)&ah,  g_attn_hi);
    cudaGetSymbolAddress((void**)&al,  g_attn_lo);

    bf16 *wdkdqh, *wdkdql, *wukvh, *wukvl, *wuqqrh, *wuqqrl, *woh, *wol;
    cudaGetSymbolAddress((void**)&wdkdqh, g_wdkdq_hi);
    cudaGetSymbolAddress((void**)&wdkdql, g_wdkdq_lo);
    cudaGetSymbolAddress((void**)&wukvh,  g_wukv_hi);
    cudaGetSymbolAddress((void**)&wukvl,  g_wukv_lo);
    cudaGetSymbolAddress((void**)&wuqqrh, g_wuqqr_hi);
    cudaGetSymbolAddress((void**)&wuqqrl, g_wuqqr_lo);
    cudaGetSymbolAddress((void**)&woh,    g_wo_hi);
    cudaGetSymbolAddress((void**)&wol,    g_wo_lo);

    rope_table_kernel<<<(LL*32 + 255) / 256, 256>>>();

    cudaMemsetAsync(wdkdqh + (size_t)2112 * 2048, 0, (size_t)64 * 2048 * sizeof(bf16));
    cudaMemsetAsync(wdkdql + (size_t)2112 * 2048, 0, (size_t)64 * 2048 * sizeof(bf16));

    dim3 tb(32, 8);
    transpose_conv<<<dim3(DCC/32,  DD/32),  tb>>>(W_DKV, wdkdqh,                     wdkdql,                     DD,  DCC);
    transpose_conv<<<dim3(DCC/32,  DD/32),  tb>>>(W_DQ,  wdkdqh + (size_t)1024*2048, wdkdql + (size_t)1024*2048, DD,  DCC);
    transpose_conv<<<dim3(DHRR/32, DD/32),  tb>>>(W_KR,  wdkdqh + (size_t)2048*2048, wdkdql + (size_t)2048*2048, DD,  DHRR);
    transpose_conv<<<dim3(DD/32,   DCC/32), tb>>>(W_UK,  wukvh,                      wukvl,                      DCC, DD);
    transpose_conv<<<dim3(DD/32,   DCC/32), tb>>>(W_UV,  wukvh + (size_t)2048*1024,  wukvl + (size_t)2048*1024,  DCC, DD);
    transpose_conv<<<dim3(DD/32,   DCC/32), tb>>>(W_UQ,  wuqqrh,                     wuqqrl,                     DCC, DD);
    transpose_conv<<<dim3(DCC/32,  DCC/32), tb>>>(W_QR,  wuqqrh + (size_t)2048*1024, wuqqrl + (size_t)2048*1024, DCC, DCC);
    transpose_conv<<<dim3(DD/32,   DD/32),  tb>>>(W_O,   woh,                        wol,                        DD,  DD);

    constexpr int SMEM128 = 3 * (2*128*128 + 2*128*128);  // 196608
    cudaFuncSetAttribute((const void*)gemm_bf16x3<128,true>,  cudaFuncAttributeMaxDynamicSharedMemorySize, SMEM128);
    cudaFuncSetAttribute((const void*)gemm_bf16x3<128,false>, cudaFuncAttributeMaxDynamicSharedMemorySize, SMEM128);

    // x -> hi/lo
    conv_hilo<<<(MTOK*DD/4 + 255) / 256, 256>>>(x, xh, xl, MTOK*DD/4);

    // fused down projections: [ckv | cq | kr | pad] = x @ [W_DKV | W_DQ | W_KR | 0]
    gemm_bf16x3<128,true><<<dim3(CCW/128, MTOK/128), 256, SMEM128>>>(
        xh, xl, DD, wdkdqh, wdkdql, nullptr, cch, ccl, CCW, DD);

    // fused up projections: [kc | vt] = ckv @ [W_UK | W_UV]
    gemm_bf16x3<128,false><<<dim3(4096/128, MTOK/128), 256, SMEM128>>>(
        cch, ccl, CCW, wukvh, wukvl, p_kcvt, nullptr, nullptr, 4096, DCC);
    // [qc | qr] = cq @ [W_UQ | W_QR]
    gemm_bf16x3<128,false><<<dim3(3072/128, MTOK/128), 256, SMEM128>>>(
        cch + 1024, ccl + 1024, CCW, wuqqrh, wuqqrl, p_qcqr, nullptr, nullptr, 3072, DCC);

    // pack q/k (hi/lo bf16) + V^T (hi/lo bf16)
    pack_kernel<<<(BB*LL*NHH)/8, 256>>>(s_qk);
    v_transpose_kernel<<<dim3(DHH/32, LL/32, BHT), tb>>>();

    // tensor-core flash attention (heavy q-tiles first)
    cudaFuncSetAttribute(attn_mma_kernel, cudaFuncAttributeMaxDynamicSharedMemorySize, AT_SMEM);
    attn_mma_kernel<<<dim3(BHT, LL/128), 256, AT_SMEM>>>();

    // output projection
    gemm_bf16x3<128,false><<<dim3(DD/128, MTOK/128), 256, SMEM128>>>(
        ah, al, DD, woh, wol, out, nullptr, nullptr, DD, DD);
}